// round 4
// baseline (speedup 1.0000x reference)
#include <cuda_runtime.h>

// ---------------------------------------------------------------------------
// CrossAttention, fp32 baseline:
//   Kp = K @ Wk^T + bk          [4,2048,1024]
//   Vp = V @ Wv^T + bv          [4,2048,1024]
//   S  = (Q @ Kp^T) / 32        [4,1024,2048]
//   P  = softmax_rows(S)
//   C  = P @ Vp                 [4,1024,1024]
//   O  = C @ Wo^T + bo          [4,1024,1024]
// All matrix dims divide the 128x128x16 tiles exactly -> no bounds checks.
// ---------------------------------------------------------------------------

#define BATCH 4
#define LQ    1024
#define LK    2048
#define D1    1024
#define D2    1280

// Scratch (static device globals: allocation-free per harness rules)
__device__ float g_Kp [BATCH * LK * D1];   // 32 MB
__device__ float g_Vp [BATCH * LK * D1];   // 32 MB
__device__ float g_S  [BATCH * LQ * LK];   // 32 MB
__device__ float g_ctx[BATCH * LQ * D1];   // 16 MB

// ---------------------------------------------------------------------------
// Tiled GEMM.
//   TRANSB = true : C[m,n] = alpha * sum_k A[m,k] * B[n,k]  (+bias[n])
//                   (both operands K-contiguous; used for x @ W^T and Q @ Kp^T)
//   TRANSB = false: C[m,n] = alpha * sum_k A[m,k] * B[k,n]  (+bias[n])
//                   (used for P @ Vp)
// BM=BN=128, BK=16, 256 threads, 8x8 per-thread micro-tile.
// Requires: M%128==0, N%128==0, Kd%16==0, ldA=Kd, ldC=N.
// ---------------------------------------------------------------------------
template<bool TRANSB>
__global__ __launch_bounds__(256, 2)
void gemm_tile(const float* __restrict__ A,
               const float* __restrict__ Bm,
               const float* __restrict__ bias,
               float* __restrict__ C,
               int M, int N, int Kd,
               size_t strideA, size_t strideB, size_t strideC,
               float alpha)
{
    __shared__ float As[16][128];
    __shared__ float Bs[16][128];

    const int bx = blockIdx.x;           // N tile index
    const int by = blockIdx.y;           // M tile index
    const int bz = blockIdx.z;           // batch
    A  += (size_t)bz * strideA;
    Bm += (size_t)bz * strideB;
    C  += (size_t)bz * strideC;

    const int tid  = threadIdx.x;
    const int tx   = tid & 15;           // 0..15
    const int ty   = tid >> 4;           // 0..15
    const int row0 = by * 128 + ty * 8;
    const int col0 = bx * 128 + tx * 8;

    float acc[8][8];
    #pragma unroll
    for (int i = 0; i < 8; i++)
        #pragma unroll
        for (int j = 0; j < 8; j++)
            acc[i][j] = 0.0f;

    for (int k0 = 0; k0 < Kd; k0 += 16) {
        // ---- stage A tile (transposed: As[k][m]) ----
        {
            int idx = tid;
            #pragma unroll
            for (int r = 0; r < 2; r++, idx += 256) {
                int arow = idx >> 2;                 // 0..127
                int acol = (idx & 3) << 2;           // 0,4,8,12
                float4 v = *reinterpret_cast<const float4*>(
                    &A[(size_t)(by * 128 + arow) * Kd + k0 + acol]);
                As[acol + 0][arow] = v.x;
                As[acol + 1][arow] = v.y;
                As[acol + 2][arow] = v.z;
                As[acol + 3][arow] = v.w;
            }
        }
        // ---- stage B tile (Bs[k][n]) ----
        if (TRANSB) {
            int idx = tid;
            #pragma unroll
            for (int r = 0; r < 2; r++, idx += 256) {
                int brow = idx >> 2;                 // n within tile
                int bcol = (idx & 3) << 2;           // k within tile
                float4 v = *reinterpret_cast<const float4*>(
                    &Bm[(size_t)(bx * 128 + brow) * Kd + k0 + bcol]);
                Bs[bcol + 0][brow] = v.x;
                Bs[bcol + 1][brow] = v.y;
                Bs[bcol + 2][brow] = v.z;
                Bs[bcol + 3][brow] = v.w;
            }
        } else {
            int idx = tid;
            #pragma unroll
            for (int r = 0; r < 2; r++, idx += 256) {
                int krow = idx >> 5;                 // 0..15
                int ncol = (idx & 31) << 2;          // 0..124
                float4 v = *reinterpret_cast<const float4*>(
                    &Bm[(size_t)(k0 + krow) * N + bx * 128 + ncol]);
                *reinterpret_cast<float4*>(&Bs[krow][ncol]) = v;
            }
        }
        __syncthreads();

        // ---- 8x8 FFMA micro-kernel ----
        #pragma unroll
        for (int k = 0; k < 16; k++) {
            float a[8], b[8];
            *reinterpret_cast<float4*>(&a[0]) =
                *reinterpret_cast<const float4*>(&As[k][ty * 8]);
            *reinterpret_cast<float4*>(&a[4]) =
                *reinterpret_cast<const float4*>(&As[k][ty * 8 + 4]);
            *reinterpret_cast<float4*>(&b[0]) =
                *reinterpret_cast<const float4*>(&Bs[k][tx * 8]);
            *reinterpret_cast<float4*>(&b[4]) =
                *reinterpret_cast<const float4*>(&Bs[k][tx * 8 + 4]);
            #pragma unroll
            for (int i = 0; i < 8; i++)
                #pragma unroll
                for (int j = 0; j < 8; j++)
                    acc[i][j] = fmaf(a[i], b[j], acc[i][j]);
        }
        __syncthreads();
    }

    // ---- epilogue: alpha scale + optional bias, vectorized stores ----
    float bb[8];
    #pragma unroll
    for (int j = 0; j < 8; j++)
        bb[j] = bias ? bias[col0 + j] : 0.0f;

    #pragma unroll
    for (int i = 0; i < 8; i++) {
        float4 o0, o1;
        o0.x = fmaf(acc[i][0], alpha, bb[0]);
        o0.y = fmaf(acc[i][1], alpha, bb[1]);
        o0.z = fmaf(acc[i][2], alpha, bb[2]);
        o0.w = fmaf(acc[i][3], alpha, bb[3]);
        o1.x = fmaf(acc[i][4], alpha, bb[4]);
        o1.y = fmaf(acc[i][5], alpha, bb[5]);
        o1.z = fmaf(acc[i][6], alpha, bb[6]);
        o1.w = fmaf(acc[i][7], alpha, bb[7]);
        size_t off = (size_t)(row0 + i) * N + col0;
        *reinterpret_cast<float4*>(&C[off])     = o0;
        *reinterpret_cast<float4*>(&C[off + 4]) = o1;
    }
}

// ---------------------------------------------------------------------------
// In-place row softmax over LK=2048 columns. One 256-thread block per row.
// ---------------------------------------------------------------------------
__global__ __launch_bounds__(256)
void softmax_rows_kernel(float* __restrict__ S)
{
    float* p = S + (size_t)blockIdx.x * LK;
    const int tid = threadIdx.x;

    float v[8];
    float m = -1e30f;
    #pragma unroll
    for (int i = 0; i < 8; i++) {
        v[i] = p[tid + i * 256];
        m = fmaxf(m, v[i]);
    }
    #pragma unroll
    for (int o = 16; o > 0; o >>= 1)
        m = fmaxf(m, __shfl_xor_sync(0xffffffffu, m, o));

    __shared__ float sm[8];
    if ((tid & 31) == 0) sm[tid >> 5] = m;
    __syncthreads();
    #pragma unroll
    for (int i = 0; i < 8; i++) m = fmaxf(m, sm[i]);

    float s = 0.0f;
    #pragma unroll
    for (int i = 0; i < 8; i++) {
        v[i] = __expf(v[i] - m);
        s += v[i];
    }
    #pragma unroll
    for (int o = 16; o > 0; o >>= 1)
        s += __shfl_xor_sync(0xffffffffu, s, o);

    __shared__ float ss[8];
    if ((tid & 31) == 0) ss[tid >> 5] = s;
    __syncthreads();
    s = 0.0f;
    #pragma unroll
    for (int i = 0; i < 8; i++) s += ss[i];

    const float inv = 1.0f / s;
    #pragma unroll
    for (int i = 0; i < 8; i++)
        p[tid + i * 256] = v[i] * inv;
}

// ---------------------------------------------------------------------------
// Host launch
// ---------------------------------------------------------------------------
extern "C" void kernel_launch(void* const* d_in, const int* in_sizes, int n_in,
                              void* d_out, int out_size)
{
    const float* Q  = (const float*)d_in[0];
    const float* K  = (const float*)d_in[1];
    const float* V  = (const float*)d_in[2];
    const float* Wk = (const float*)d_in[3];
    const float* bk = (const float*)d_in[4];
    const float* Wv = (const float*)d_in[5];
    const float* bv = (const float*)d_in[6];
    const float* Wo = (const float*)d_in[7];
    const float* bo = (const float*)d_in[8];
    float* out = (float*)d_out;

    float *Kp, *Vp, *S, *Ctx;
    cudaGetSymbolAddress((void**)&Kp,  g_Kp);
    cudaGetSymbolAddress((void**)&Vp,  g_Vp);
    cudaGetSymbolAddress((void**)&S,   g_S);
    cudaGetSymbolAddress((void**)&Ctx, g_ctx);

    const dim3 blk(256);

    // 1) K projection: [B*LK, D2] @ Wk^T -> [B*LK, D1]
    gemm_tile<true><<<dim3(D1 / 128, (BATCH * LK) / 128, 1), blk>>>(
        K, Wk, bk, Kp, BATCH * LK, D1, D2, 0, 0, 0, 1.0f);

    // 2) V projection
    gemm_tile<true><<<dim3(D1 / 128, (BATCH * LK) / 128, 1), blk>>>(
        V, Wv, bv, Vp, BATCH * LK, D1, D2, 0, 0, 0, 1.0f);

    // 3) scores: per-batch Q [LQ,D1] @ Kp^T [LK,D1] -> S [LQ,LK], scaled 1/32
    gemm_tile<true><<<dim3(LK / 128, LQ / 128, BATCH), blk>>>(
        Q, Kp, nullptr, S, LQ, LK, D1,
        (size_t)LQ * D1, (size_t)LK * D1, (size_t)LQ * LK, 0.03125f);

    // 4) softmax over last axis, one block per row
    softmax_rows_kernel<<<BATCH * LQ, blk>>>(S);

    // 5) context: per-batch P [LQ,LK] @ Vp [LK,D1] -> Ctx [LQ,D1]
    gemm_tile<false><<<dim3(D1 / 128, LQ / 128, BATCH), blk>>>(
        S, Vp, nullptr, Ctx, LQ, D1, LK,
        (size_t)LQ * LK, (size_t)LK * D1, (size_t)LQ * D1, 1.0f);

    // 6) output: [B*LQ, D1] @ Wo^T + bo -> out
    gemm_tile<true><<<dim3(D1 / 128, (BATCH * LQ) / 128, 1), blk>>>(
        Ctx, Wo, bo, out, BATCH * LQ, D1, D1, 0, 0, 0, 1.0f);
}

// round 7
// speedup vs baseline: 4.2893x; 4.2893x over previous
#include <cuda_runtime.h>

// ---------------------------------------------------------------------------
// CrossAttention, tf32 tensor-core version (mma.sync.m16n8k8.tf32):
//   Kp = K @ Wk^T + bk          [4,2048,1024]
//   Vp = V @ Wv^T + bv          [4,2048,1024]
//   S  = (Q @ Kp^T) / 32        [4,1024,2048]
//   P  = softmax_rows(S)
//   C  = P @ Vp                 [4,1024,1024]
//   O  = C @ Wo^T + bo          [4,1024,1024]
// All dims divide 128x128x32 tiles exactly -> no bounds checks.
// ---------------------------------------------------------------------------

#define BATCH 4
#define LQ    1024
#define LK    2048
#define D1    1024
#define D2    1280

__device__ float g_Kp [BATCH * LK * D1];   // 32 MB
__device__ float g_Vp [BATCH * LK * D1];   // 32 MB
__device__ float g_S  [BATCH * LQ * LK];   // 32 MB
__device__ float g_ctx[BATCH * LQ * D1];   // 16 MB

// Padded leading dim: 36 floats = 144 B (16B-aligned rows, and fragment-load
// bank = (4*m + k) mod 32 is a bijection across the warp -> conflict-free).
#define LDK 36

__device__ __forceinline__ unsigned f2tf32(float x) {
    unsigned u;
    asm("cvt.rna.tf32.f32 %0, %1;" : "=r"(u) : "f"(x));
    return u;
}

__device__ __forceinline__ void mma_tf32(float c[4],
                                         unsigned a0, unsigned a1,
                                         unsigned a2, unsigned a3,
                                         unsigned b0, unsigned b1) {
    asm volatile(
        "mma.sync.aligned.m16n8k8.row.col.f32.tf32.tf32.f32 "
        "{%0,%1,%2,%3}, {%4,%5,%6,%7}, {%8,%9}, {%0,%1,%2,%3};"
        : "+f"(c[0]), "+f"(c[1]), "+f"(c[2]), "+f"(c[3])
        : "r"(a0), "r"(a1), "r"(a2), "r"(a3), "r"(b0), "r"(b1));
}

// ---------------------------------------------------------------------------
// Tensor-core GEMM.
//   TRANSB=true : C[m,n] = alpha * sum_k A[m,k]*B[n,k] (+bias[n])
//   TRANSB=false: C[m,n] = alpha * sum_k A[m,k]*B[k,n] (+bias[n])
// BM=BN=128, BK=32, 256 threads = 8 warps (2 x 4), warp tile 64x32.
// Requires: M%128==0, N%128==0, Kd%32==0, ldA=Kd, ldC=N.
// ---------------------------------------------------------------------------
template<bool TRANSB>
__global__ __launch_bounds__(256, 2)
void gemm_mma(const float* __restrict__ A,
              const float* __restrict__ Bm,
              const float* __restrict__ bias,
              float* __restrict__ C,
              int M, int N, int Kd,
              size_t sA, size_t sB, size_t sC,
              float alpha)
{
    __shared__ unsigned As[128 * LDK];   // [m][k], tf32 bits
    __shared__ unsigned Bs[128 * LDK];   // [n][k], tf32 bits

    const int bx = blockIdx.x, by = blockIdx.y, bz = blockIdx.z;
    A  += (size_t)bz * sA;
    Bm += (size_t)bz * sB;
    C  += (size_t)bz * sC;

    const int tid  = threadIdx.x;
    const int warp = tid >> 5, lane = tid & 31;
    const int wm = warp >> 2;            // 0..1  (64 rows each)
    const int wn = warp & 3;             // 0..3  (32 cols each)
    const int lq = lane >> 2;            // 0..7
    const int lr = lane & 3;             // 0..3

    float acc[4][4][4];
    #pragma unroll
    for (int mt = 0; mt < 4; mt++)
        #pragma unroll
        for (int nt = 0; nt < 4; nt++)
            #pragma unroll
            for (int i = 0; i < 4; i++)
                acc[mt][nt][i] = 0.0f;

    for (int k0 = 0; k0 < Kd; k0 += 32) {
        // ---- stage A tile: 128 x 32, row-major, cvt to tf32 ----
        #pragma unroll
        for (int r = 0; r < 4; r++) {
            int f  = tid + r * 256;      // 0..1023
            int m  = f >> 3;             // 0..127
            int kc = f & 7;              // float4 chunk 0..7
            float4 v = *reinterpret_cast<const float4*>(
                &A[(size_t)(by * 128 + m) * Kd + k0 + kc * 4]);
            uint4 u = make_uint4(f2tf32(v.x), f2tf32(v.y), f2tf32(v.z), f2tf32(v.w));
            *reinterpret_cast<uint4*>(&As[m * LDK + kc * 4]) = u;
        }
        // ---- stage B tile into [n][k] layout ----
        if (TRANSB) {
            #pragma unroll
            for (int r = 0; r < 4; r++) {
                int f  = tid + r * 256;
                int n  = f >> 3;
                int kc = f & 7;
                float4 v = *reinterpret_cast<const float4*>(
                    &Bm[(size_t)(bx * 128 + n) * Kd + k0 + kc * 4]);
                uint4 u = make_uint4(f2tf32(v.x), f2tf32(v.y), f2tf32(v.z), f2tf32(v.w));
                *reinterpret_cast<uint4*>(&Bs[n * LDK + kc * 4]) = u;
            }
        } else {
            // B is [k][n]: coalesced reads along n, transpose into Bs[n][k]
            #pragma unroll
            for (int r = 0; r < 4; r++) {
                int f  = tid + r * 256;
                int kr = f >> 5;             // 0..31
                int nc = f & 31;             // float4 chunk over n
                float4 v = *reinterpret_cast<const float4*>(
                    &Bm[(size_t)(k0 + kr) * N + bx * 128 + nc * 4]);
                Bs[(nc * 4 + 0) * LDK + kr] = f2tf32(v.x);
                Bs[(nc * 4 + 1) * LDK + kr] = f2tf32(v.y);
                Bs[(nc * 4 + 2) * LDK + kr] = f2tf32(v.z);
                Bs[(nc * 4 + 3) * LDK + kr] = f2tf32(v.w);
            }
        }
        __syncthreads();

        // ---- 4 k8-steps of 16 MMAs each ----
        #pragma unroll
        for (int ks = 0; ks < 4; ks++) {
            const int kk = ks * 8;
            unsigned af[4][4], bf[4][2];
            #pragma unroll
            for (int mt = 0; mt < 4; mt++) {
                int m = wm * 64 + mt * 16 + lq;
                af[mt][0] = As[m * LDK + kk + lr];
                af[mt][1] = As[(m + 8) * LDK + kk + lr];
                af[mt][2] = As[m * LDK + kk + 4 + lr];
                af[mt][3] = As[(m + 8) * LDK + kk + 4 + lr];
            }
            #pragma unroll
            for (int nt = 0; nt < 4; nt++) {
                int n = wn * 32 + nt * 8 + lq;
                bf[nt][0] = Bs[n * LDK + kk + lr];
                bf[nt][1] = Bs[n * LDK + kk + 4 + lr];
            }
            #pragma unroll
            for (int mt = 0; mt < 4; mt++)
                #pragma unroll
                for (int nt = 0; nt < 4; nt++)
                    mma_tf32(acc[mt][nt],
                             af[mt][0], af[mt][1], af[mt][2], af[mt][3],
                             bf[nt][0], bf[nt][1]);
        }
        __syncthreads();
    }

    // ---- epilogue: alpha + optional bias, float2 stores ----
    #pragma unroll
    for (int mt = 0; mt < 4; mt++) {
        int row = by * 128 + wm * 64 + mt * 16 + lq;
        #pragma unroll
        for (int nt = 0; nt < 4; nt++) {
            int col = bx * 128 + wn * 32 + nt * 8 + 2 * lr;
            float b0 = bias ? bias[col]     : 0.0f;
            float b1 = bias ? bias[col + 1] : 0.0f;
            float2 v0, v1;
            v0.x = fmaf(acc[mt][nt][0], alpha, b0);
            v0.y = fmaf(acc[mt][nt][1], alpha, b1);
            v1.x = fmaf(acc[mt][nt][2], alpha, b0);
            v1.y = fmaf(acc[mt][nt][3], alpha, b1);
            *reinterpret_cast<float2*>(&C[(size_t)row * N + col])       = v0;
            *reinterpret_cast<float2*>(&C[(size_t)(row + 8) * N + col]) = v1;
        }
    }
}

// ---------------------------------------------------------------------------
// In-place row softmax over LK=2048 columns. One 256-thread block per row.
// ---------------------------------------------------------------------------
__global__ __launch_bounds__(256)
void softmax_rows_kernel(float* __restrict__ S)
{
    float* p = S + (size_t)blockIdx.x * LK;
    const int tid = threadIdx.x;

    float v[8];
    float m = -1e30f;
    #pragma unroll
    for (int i = 0; i < 8; i++) {
        v[i] = p[tid + i * 256];
        m = fmaxf(m, v[i]);
    }
    #pragma unroll
    for (int o = 16; o > 0; o >>= 1)
        m = fmaxf(m, __shfl_xor_sync(0xffffffffu, m, o));

    __shared__ float sm[8];
    if ((tid & 31) == 0) sm[tid >> 5] = m;
    __syncthreads();
    #pragma unroll
    for (int i = 0; i < 8; i++) m = fmaxf(m, sm[i]);

    float s = 0.0f;
    #pragma unroll
    for (int i = 0; i < 8; i++) {
        v[i] = __expf(v[i] - m);
        s += v[i];
    }
    #pragma unroll
    for (int o = 16; o > 0; o >>= 1)
        s += __shfl_xor_sync(0xffffffffu, s, o);

    __shared__ float ss[8];
    if ((tid & 31) == 0) ss[tid >> 5] = s;
    __syncthreads();
    s = 0.0f;
    #pragma unroll
    for (int i = 0; i < 8; i++) s += ss[i];

    const float inv = 1.0f / s;
    #pragma unroll
    for (int i = 0; i < 8; i++)
        p[tid + i * 256] = v[i] * inv;
}

// ---------------------------------------------------------------------------
// Host launch
// ---------------------------------------------------------------------------
extern "C" void kernel_launch(void* const* d_in, const int* in_sizes, int n_in,
                              void* d_out, int out_size)
{
    const float* Q  = (const float*)d_in[0];
    const float* K  = (const float*)d_in[1];
    const float* V  = (const float*)d_in[2];
    const float* Wk = (const float*)d_in[3];
    const float* bk = (const float*)d_in[4];
    const float* Wv = (const float*)d_in[5];
    const float* bv = (const float*)d_in[6];
    const float* Wo = (const float*)d_in[7];
    const float* bo = (const float*)d_in[8];
    float* out = (float*)d_out;

    float *Kp, *Vp, *S, *Ctx;
    cudaGetSymbolAddress((void**)&Kp,  g_Kp);
    cudaGetSymbolAddress((void**)&Vp,  g_Vp);
    cudaGetSymbolAddress((void**)&S,   g_S);
    cudaGetSymbolAddress((void**)&Ctx, g_ctx);

    const dim3 blk(256);

    // 1) K projection: [B*LK, D2] @ Wk^T -> [B*LK, D1]
    gemm_mma<true><<<dim3(D1 / 128, (BATCH * LK) / 128, 1), blk>>>(
        K, Wk, bk, Kp, BATCH * LK, D1, D2, 0, 0, 0, 1.0f);

    // 2) V projection
    gemm_mma<true><<<dim3(D1 / 128, (BATCH * LK) / 128, 1), blk>>>(
        V, Wv, bv, Vp, BATCH * LK, D1, D2, 0, 0, 0, 1.0f);

    // 3) scores: per-batch Q [LQ,D1] @ Kp^T [LK,D1] -> S [LQ,LK], scaled 1/32
    gemm_mma<true><<<dim3(LK / 128, LQ / 128, BATCH), blk>>>(
        Q, Kp, nullptr, S, LQ, LK, D1,
        (size_t)LQ * D1, (size_t)LK * D1, (size_t)LQ * LK, 0.03125f);

    // 4) softmax over last axis, one block per row
    softmax_rows_kernel<<<BATCH * LQ, blk>>>(S);

    // 5) context: per-batch P [LQ,LK] @ Vp [LK,D1] -> Ctx [LQ,D1]
    gemm_mma<false><<<dim3(D1 / 128, LQ / 128, BATCH), blk>>>(
        S, Vp, nullptr, Ctx, LQ, D1, LK,
        (size_t)LQ * LK, (size_t)LK * D1, (size_t)LQ * D1, 1.0f);

    // 6) output: [B*LQ, D1] @ Wo^T + bo -> out
    gemm_mma<true><<<dim3(D1 / 128, (BATCH * LQ) / 128, 1), blk>>>(
        Ctx, Wo, bo, out, BATCH * LQ, D1, D1, 0, 0, 0, 1.0f);
}

// round 9
// speedup vs baseline: 4.3518x; 1.0146x over previous
#include <cuda_runtime.h>

// ---------------------------------------------------------------------------
// CrossAttention, tf32 mma.sync, 256x128x16 CTA tile, 64x64 warp tiles,
// double-buffered smem with register-staged global prefetch.
//   Kp = K @ Wk^T + bk          [4,2048,1024]
//   Vp = V @ Wv^T + bv          [4,2048,1024]
//   S  = (Q @ Kp^T) / 32        [4,1024,2048]
//   P  = softmax_rows(S)
//   C  = P @ Vp                 [4,1024,1024]
//   O  = C @ Wo^T + bo          [4,1024,1024]
// All dims divide 256x128x16 tiles exactly -> no bounds checks.
// ---------------------------------------------------------------------------

#define BATCH 4
#define LQ    1024
#define LK    2048
#define D1    1024
#define D2    1280

__device__ float g_Kp [BATCH * LK * D1];
__device__ float g_Vp [BATCH * LK * D1];
__device__ float g_S  [BATCH * LQ * LK];
__device__ float g_ctx[BATCH * LQ * D1];

#define LDK 20                    // 16 + 4 pad: conflict-free fragment LDS
#define A_U32 (256 * LDK)         // 5120
#define B_U32 (128 * LDK)         // 2560
#define STAGE_U32 (A_U32 + B_U32) // 7680
#define SMEM_BYTES (2 * STAGE_U32 * 4)  // 61440

__device__ __forceinline__ unsigned f2tf32(float x) {
    unsigned u;
    asm("cvt.rna.tf32.f32 %0, %1;" : "=r"(u) : "f"(x));
    return u;
}

__device__ __forceinline__ void mma_tf32(float c[4],
                                         unsigned a0, unsigned a1,
                                         unsigned a2, unsigned a3,
                                         unsigned b0, unsigned b1) {
    asm volatile(
        "mma.sync.aligned.m16n8k8.row.col.f32.tf32.tf32.f32 "
        "{%0,%1,%2,%3}, {%4,%5,%6,%7}, {%8,%9}, {%0,%1,%2,%3};"
        : "+f"(c[0]), "+f"(c[1]), "+f"(c[2]), "+f"(c[3])
        : "r"(a0), "r"(a1), "r"(a2), "r"(a3), "r"(b0), "r"(b1));
}

// ---------------------------------------------------------------------------
//   TRANSB=true : C[m,n] = alpha * sum_k A[m,k]*B[n,k] (+bias[n])
//   TRANSB=false: C[m,n] = alpha * sum_k A[m,k]*B[k,n] (+bias[n])
// BM=256, BN=128, BK=16, 256 threads = 8 warps (4m x 2n), warp tile 64x64.
// Requires: M%256==0, N%128==0, Kd%16==0, ldA=Kd, ldC=N.
// ---------------------------------------------------------------------------
template<bool TRANSB>
__global__ __launch_bounds__(256, 1)
void gemm_mma(const float* __restrict__ A,
              const float* __restrict__ Bm,
              const float* __restrict__ bias,
              float* __restrict__ C,
              int N, int Kd,
              size_t sA, size_t sB, size_t sC,
              float alpha)
{
    extern __shared__ unsigned sh[];

    const int bx = blockIdx.x, by = blockIdx.y, bz = blockIdx.z;
    A  += (size_t)bz * sA;
    Bm += (size_t)bz * sB;
    C  += (size_t)bz * sC;

    const int tid  = threadIdx.x;
    const int warp = tid >> 5, lane = tid & 31;
    const int wm = warp >> 1;            // 0..3  (64 rows each)
    const int wn = warp & 1;             // 0..1  (64 cols each)
    const int lq = lane >> 2;            // 0..7
    const int lr = lane & 3;             // 0..3

    // ---- per-thread staging geometry ----
    // A: 4 float4 chunks: rows m = (tid>>2)+{0,64,128,192}, col-chunk kc=tid&3
    const int a_m0 = tid >> 2;
    const int kc   = tid & 3;
    const float* a_ptr = A + (size_t)(by * 256 + a_m0) * Kd + kc * 4;

    // B geometry
    const float* b_ptr;
    int b_n0 = 0, b_kr0 = 0, b_ncw = 0;
    if (TRANSB) {
        b_n0  = tid >> 2;                // rows n0, n0+64
        b_ptr = Bm + (size_t)(bx * 128 + b_n0) * Kd + kc * 4;
    } else {
        b_kr0 = tid >> 5;                // k rows kr0, kr0+8
        b_ncw = tid & 31;                // n float4 chunk
        b_ptr = Bm + (size_t)b_kr0 * N + bx * 128 + b_ncw * 4;
    }

    float acc[4][8][4];
    #pragma unroll
    for (int mt = 0; mt < 4; mt++)
        #pragma unroll
        for (int nt = 0; nt < 8; nt++)
            #pragma unroll
            for (int i = 0; i < 4; i++)
                acc[mt][nt][i] = 0.0f;

    float4 ar[4], br[2];

    // ---- prefetch tile 0 ----
    #pragma unroll
    for (int i = 0; i < 4; i++)
        ar[i] = *reinterpret_cast<const float4*>(a_ptr + (size_t)(i * 64) * Kd);
    if (TRANSB) {
        #pragma unroll
        for (int i = 0; i < 2; i++)
            br[i] = *reinterpret_cast<const float4*>(b_ptr + (size_t)(i * 64) * Kd);
    } else {
        #pragma unroll
        for (int i = 0; i < 2; i++)
            br[i] = *reinterpret_cast<const float4*>(b_ptr + (size_t)(i * 8) * N);
    }

    // ---- store tile 0 into stage 0 ----
    {
        unsigned* As = sh;
        unsigned* Bs = sh + A_U32;
        #pragma unroll
        for (int i = 0; i < 4; i++) {
            uint4 u = make_uint4(f2tf32(ar[i].x), f2tf32(ar[i].y),
                                 f2tf32(ar[i].z), f2tf32(ar[i].w));
            *reinterpret_cast<uint4*>(&As[(a_m0 + i * 64) * LDK + kc * 4]) = u;
        }
        if (TRANSB) {
            #pragma unroll
            for (int i = 0; i < 2; i++) {
                uint4 u = make_uint4(f2tf32(br[i].x), f2tf32(br[i].y),
                                     f2tf32(br[i].z), f2tf32(br[i].w));
                *reinterpret_cast<uint4*>(&Bs[(b_n0 + i * 64) * LDK + kc * 4]) = u;
            }
        } else {
            #pragma unroll
            for (int i = 0; i < 2; i++) {
                int kr = b_kr0 + i * 8;
                Bs[(b_ncw * 4 + 0) * LDK + kr] = f2tf32(br[i].x);
                Bs[(b_ncw * 4 + 1) * LDK + kr] = f2tf32(br[i].y);
                Bs[(b_ncw * 4 + 2) * LDK + kr] = f2tf32(br[i].z);
                Bs[(b_ncw * 4 + 3) * LDK + kr] = f2tf32(br[i].w);
            }
        }
    }
    __syncthreads();

    const int NT = Kd >> 4;
    for (int t = 0; t < NT; t++) {
        // ---- prefetch tile t+1 into registers (global latency hides under MMA) ----
        if (t + 1 < NT) {
            const float* ap = a_ptr + (t + 1) * 16;
            #pragma unroll
            for (int i = 0; i < 4; i++)
                ar[i] = *reinterpret_cast<const float4*>(ap + (size_t)(i * 64) * Kd);
            if (TRANSB) {
                const float* bp = b_ptr + (t + 1) * 16;
                #pragma unroll
                for (int i = 0; i < 2; i++)
                    br[i] = *reinterpret_cast<const float4*>(bp + (size_t)(i * 64) * Kd);
            } else {
                const float* bp = b_ptr + (size_t)(t + 1) * 16 * N;
                #pragma unroll
                for (int i = 0; i < 2; i++)
                    br[i] = *reinterpret_cast<const float4*>(bp + (size_t)(i * 8) * N);
            }
        }

        // ---- compute from stage t&1 ----
        {
            const unsigned* As = sh + (t & 1) * STAGE_U32;
            const unsigned* Bs = As + A_U32;
            #pragma unroll
            for (int ks = 0; ks < 2; ks++) {
                const int kk = ks * 8;
                unsigned af[4][4], bf[8][2];
                #pragma unroll
                for (int mt = 0; mt < 4; mt++) {
                    int m = wm * 64 + mt * 16 + lq;
                    af[mt][0] = As[m * LDK + kk + lr];
                    af[mt][1] = As[(m + 8) * LDK + kk + lr];
                    af[mt][2] = As[m * LDK + kk + 4 + lr];
                    af[mt][3] = As[(m + 8) * LDK + kk + 4 + lr];
                }
                #pragma unroll
                for (int nt = 0; nt < 8; nt++) {
                    int n = wn * 64 + nt * 8 + lq;
                    bf[nt][0] = Bs[n * LDK + kk + lr];
                    bf[nt][1] = Bs[n * LDK + kk + 4 + lr];
                }
                #pragma unroll
                for (int mt = 0; mt < 4; mt++)
                    #pragma unroll
                    for (int nt = 0; nt < 8; nt++)
                        mma_tf32(acc[mt][nt],
                                 af[mt][0], af[mt][1], af[mt][2], af[mt][3],
                                 bf[nt][0], bf[nt][1]);
            }
        }

        // ---- cvt + store tile t+1 into the other stage ----
        if (t + 1 < NT) {
            unsigned* As = sh + ((t + 1) & 1) * STAGE_U32;
            unsigned* Bs = As + A_U32;
            #pragma unroll
            for (int i = 0; i < 4; i++) {
                uint4 u = make_uint4(f2tf32(ar[i].x), f2tf32(ar[i].y),
                                     f2tf32(ar[i].z), f2tf32(ar[i].w));
                *reinterpret_cast<uint4*>(&As[(a_m0 + i * 64) * LDK + kc * 4]) = u;
            }
            if (TRANSB) {
                #pragma unroll
                for (int i = 0; i < 2; i++) {
                    uint4 u = make_uint4(f2tf32(br[i].x), f2tf32(br[i].y),
                                         f2tf32(br[i].z), f2tf32(br[i].w));
                    *reinterpret_cast<uint4*>(&Bs[(b_n0 + i * 64) * LDK + kc * 4]) = u;
                }
            } else {
                #pragma unroll
                for (int i = 0; i < 2; i++) {
                    int kr = b_kr0 + i * 8;
                    Bs[(b_ncw * 4 + 0) * LDK + kr] = f2tf32(br[i].x);
                    Bs[(b_ncw * 4 + 1) * LDK + kr] = f2tf32(br[i].y);
                    Bs[(b_ncw * 4 + 2) * LDK + kr] = f2tf32(br[i].z);
                    Bs[(b_ncw * 4 + 3) * LDK + kr] = f2tf32(br[i].w);
                }
            }
        }
        __syncthreads();
    }

    // ---- epilogue: alpha + optional bias ----
    #pragma unroll
    for (int mt = 0; mt < 4; mt++) {
        int row = by * 256 + wm * 64 + mt * 16 + lq;
        #pragma unroll
        for (int nt = 0; nt < 8; nt++) {
            int col = bx * 128 + wn * 64 + nt * 8 + 2 * lr;
            float b0 = bias ? bias[col]     : 0.0f;
            float b1 = bias ? bias[col + 1] : 0.0f;
            float2 v0, v1;
            v0.x = fmaf(acc[mt][nt][0], alpha, b0);
            v0.y = fmaf(acc[mt][nt][1], alpha, b1);
            v1.x = fmaf(acc[mt][nt][2], alpha, b0);
            v1.y = fmaf(acc[mt][nt][3], alpha, b1);
            *reinterpret_cast<float2*>(&C[(size_t)row * N + col])       = v0;
            *reinterpret_cast<float2*>(&C[(size_t)(row + 8) * N + col]) = v1;
        }
    }
}

// ---------------------------------------------------------------------------
// In-place row softmax over LK=2048 columns. One 256-thread block per row.
// ---------------------------------------------------------------------------
__global__ __launch_bounds__(256)
void softmax_rows_kernel(float* __restrict__ S)
{
    float* p = S + (size_t)blockIdx.x * LK;
    const int tid = threadIdx.x;

    float v[8];
    float m = -1e30f;
    #pragma unroll
    for (int i = 0; i < 8; i++) {
        v[i] = p[tid + i * 256];
        m = fmaxf(m, v[i]);
    }
    #pragma unroll
    for (int o = 16; o > 0; o >>= 1)
        m = fmaxf(m, __shfl_xor_sync(0xffffffffu, m, o));

    __shared__ float sm[8];
    if ((tid & 31) == 0) sm[tid >> 5] = m;
    __syncthreads();
    #pragma unroll
    for (int i = 0; i < 8; i++) m = fmaxf(m, sm[i]);

    float s = 0.0f;
    #pragma unroll
    for (int i = 0; i < 8; i++) {
        v[i] = __expf(v[i] - m);
        s += v[i];
    }
    #pragma unroll
    for (int o = 16; o > 0; o >>= 1)
        s += __shfl_xor_sync(0xffffffffu, s, o);

    __shared__ float ss[8];
    if ((tid & 31) == 0) ss[tid >> 5] = s;
    __syncthreads();
    s = 0.0f;
    #pragma unroll
    for (int i = 0; i < 8; i++) s += ss[i];

    const float inv = 1.0f / s;
    #pragma unroll
    for (int i = 0; i < 8; i++)
        p[tid + i * 256] = v[i] * inv;
}

// ---------------------------------------------------------------------------
// Host launch
// ---------------------------------------------------------------------------
extern "C" void kernel_launch(void* const* d_in, const int* in_sizes, int n_in,
                              void* d_out, int out_size)
{
    const float* Q  = (const float*)d_in[0];
    const float* K  = (const float*)d_in[1];
    const float* V  = (const float*)d_in[2];
    const float* Wk = (const float*)d_in[3];
    const float* bk = (const float*)d_in[4];
    const float* Wv = (const float*)d_in[5];
    const float* bv = (const float*)d_in[6];
    const float* Wo = (const float*)d_in[7];
    const float* bo = (const float*)d_in[8];
    float* out = (float*)d_out;

    float *Kp, *Vp, *S, *Ctx;
    cudaGetSymbolAddress((void**)&Kp,  g_Kp);
    cudaGetSymbolAddress((void**)&Vp,  g_Vp);
    cudaGetSymbolAddress((void**)&S,   g_S);
    cudaGetSymbolAddress((void**)&Ctx, g_ctx);

    cudaFuncSetAttribute(gemm_mma<true>,
        cudaFuncAttributeMaxDynamicSharedMemorySize, SMEM_BYTES);
    cudaFuncSetAttribute(gemm_mma<false>,
        cudaFuncAttributeMaxDynamicSharedMemorySize, SMEM_BYTES);

    const dim3 blk(256);

    // 1) K projection: [B*LK, D2] @ Wk^T -> [B*LK, D1]
    gemm_mma<true><<<dim3(D1 / 128, (BATCH * LK) / 256, 1), blk, SMEM_BYTES>>>(
        K, Wk, bk, Kp, D1, D2, 0, 0, 0, 1.0f);

    // 2) V projection
    gemm_mma<true><<<dim3(D1 / 128, (BATCH * LK) / 256, 1), blk, SMEM_BYTES>>>(
        V, Wv, bv, Vp, D1, D2, 0, 0, 0, 1.0f);

    // 3) scores: per-batch Q [LQ,D1] @ Kp^T [LK,D1] -> S [LQ,LK], scaled 1/32
    gemm_mma<true><<<dim3(LK / 128, LQ / 256, BATCH), blk, SMEM_BYTES>>>(
        Q, Kp, nullptr, S, LK, D1,
        (size_t)LQ * D1, (size_t)LK * D1, (size_t)LQ * LK, 0.03125f);

    // 4) softmax over last axis, one block per row
    softmax_rows_kernel<<<BATCH * LQ, blk>>>(S);

    // 5) context: per-batch P [LQ,LK] @ Vp [LK,D1] -> Ctx [LQ,D1]
    gemm_mma<false><<<dim3(D1 / 128, LQ / 256, BATCH), blk, SMEM_BYTES>>>(
        S, Vp, nullptr, Ctx, D1, LK,
        (size_t)LQ * LK, (size_t)LK * D1, (size_t)LQ * D1, 1.0f);

    // 6) output: [B*LQ, D1] @ Wo^T + bo -> out
    gemm_mma<true><<<dim3(D1 / 128, (BATCH * LQ) / 256, 1), blk, SMEM_BYTES>>>(
        Ctx, Wo, bo, out, D1, D1, 0, 0, 0, 1.0f);
}

// round 10
// speedup vs baseline: 7.7194x; 1.7739x over previous
#include <cuda_runtime.h>
#include <cuda_fp16.h>

// ---------------------------------------------------------------------------
// CrossAttention, fp16 mma.sync.m16n8k16 (fp32 accumulate).
// fp16 mantissa == tf32 mantissa (10 bits) -> same accuracy, 2x MACs/instr.
//   Kp = K @ Wk^T + bk          [4,2048,1024]
//   Vp = V @ Wv^T + bv          [4,2048,1024]
//   S  = (Q @ Kp^T) / 32        [4,1024,2048]
//   P  = softmax_rows(S)
//   C  = P @ Vp                 [4,1024,1024]
//   O  = C @ Wo^T + bo          [4,1024,1024]
// CTA tile 256x128x32, 8 warps (4m x 2n), warp tile 64x64, double-buffered.
// ---------------------------------------------------------------------------

#define BATCH 4
#define LQ    1024
#define LK    2048
#define D1    1024
#define D2    1280

__device__ float g_Kp [BATCH * LK * D1];
__device__ float g_Vp [BATCH * LK * D1];
__device__ float g_S  [BATCH * LQ * LK];
__device__ float g_ctx[BATCH * LQ * D1];

#define BK    32
#define LDKH  40                       // 32 + 8 pad (halfs): conflict-free frags
#define A_H   (256 * LDKH)             // 10240 halfs
#define B_H   (128 * LDKH)             // 5120 halfs
#define STAGE_H (A_H + B_H)            // 15360 halfs = 30720 B
#define SMEM_BYTES (2 * STAGE_H * 2)   // 61440 B

__device__ __forceinline__ void mma_f16(float c[4],
                                        unsigned a0, unsigned a1,
                                        unsigned a2, unsigned a3,
                                        unsigned b0, unsigned b1) {
    asm volatile(
        "mma.sync.aligned.m16n8k16.row.col.f32.f16.f16.f32 "
        "{%0,%1,%2,%3}, {%4,%5,%6,%7}, {%8,%9}, {%0,%1,%2,%3};"
        : "+f"(c[0]), "+f"(c[1]), "+f"(c[2]), "+f"(c[3])
        : "r"(a0), "r"(a1), "r"(a2), "r"(a3), "r"(b0), "r"(b1));
}

// ---------------------------------------------------------------------------
//   TRANSB=true : C[m,n] = alpha * sum_k A[m,k]*B[n,k] (+bias[n])
//   TRANSB=false: C[m,n] = alpha * sum_k A[m,k]*B[k,n] (+bias[n])
// Requires: M%256==0, N%128==0, Kd%32==0, ldA=Kd, ldC=N.
// ---------------------------------------------------------------------------
template<bool TRANSB>
__global__ __launch_bounds__(256, 1)
void gemm_mma(const float* __restrict__ A,
              const float* __restrict__ Bm,
              const float* __restrict__ bias,
              float* __restrict__ C,
              int N, int Kd,
              size_t sA, size_t sB, size_t sC,
              float alpha)
{
    extern __shared__ __half sh[];

    const int bx = blockIdx.x, by = blockIdx.y, bz = blockIdx.z;
    A  += (size_t)bz * sA;
    Bm += (size_t)bz * sB;
    C  += (size_t)bz * sC;

    const int tid  = threadIdx.x;
    const int warp = tid >> 5, lane = tid & 31;
    const int wm = warp >> 1;            // 0..3  (64 rows)
    const int wn = warp & 1;             // 0..1  (64 cols)
    const int lq = lane >> 2;            // 0..7
    const int lr = lane & 3;             // 0..3

    // ---- staging geometry ----
    // A: 256x32 floats = 2048 float4 -> 8 per thread.
    const int a_m0 = tid >> 3;           // 0..31, rows a_m0 + 32*i
    const int kc   = tid & 7;            // float4 chunk within BK
    const float* a_ptr = A + (size_t)(by * 256 + a_m0) * Kd + kc * 4;

    // B geometry
    const float* b_ptr;
    int b_n0 = 0, b_kr = 0, b_nc = 0;
    if (TRANSB) {
        b_n0  = tid >> 3;                // rows b_n0 + 32*i, i<4
        b_ptr = Bm + (size_t)(bx * 128 + b_n0) * Kd + kc * 4;
    } else {
        b_kr  = tid >> 5;                // k rows b_kr + 8*i, i<4
        b_nc  = tid & 31;                // float4 chunk over n
        b_ptr = Bm + (size_t)b_kr * N + bx * 128 + b_nc * 4;
    }

    float acc[4][8][4];
    #pragma unroll
    for (int mt = 0; mt < 4; mt++)
        #pragma unroll
        for (int nt = 0; nt < 8; nt++)
            #pragma unroll
            for (int i = 0; i < 4; i++)
                acc[mt][nt][i] = 0.0f;

    float4 ar[8], br[4];

    auto stage_store = [&](int stage) {
        __half* As = sh + stage * STAGE_H;
        __half* Bs = As + A_H;
        #pragma unroll
        for (int i = 0; i < 8; i++) {
            __half2* d = reinterpret_cast<__half2*>(
                &As[(a_m0 + i * 32) * LDKH + kc * 4]);
            d[0] = __floats2half2_rn(ar[i].x, ar[i].y);
            d[1] = __floats2half2_rn(ar[i].z, ar[i].w);
        }
        if (TRANSB) {
            #pragma unroll
            for (int i = 0; i < 4; i++) {
                __half2* d = reinterpret_cast<__half2*>(
                    &Bs[(b_n0 + i * 32) * LDKH + kc * 4]);
                d[0] = __floats2half2_rn(br[i].x, br[i].y);
                d[1] = __floats2half2_rn(br[i].z, br[i].w);
            }
        } else {
            #pragma unroll
            for (int i = 0; i < 4; i++) {
                int kr = b_kr + i * 8;
                Bs[(b_nc * 4 + 0) * LDKH + kr] = __float2half_rn(br[i].x);
                Bs[(b_nc * 4 + 1) * LDKH + kr] = __float2half_rn(br[i].y);
                Bs[(b_nc * 4 + 2) * LDKH + kr] = __float2half_rn(br[i].z);
                Bs[(b_nc * 4 + 3) * LDKH + kr] = __float2half_rn(br[i].w);
            }
        }
    };

    // ---- prefetch + store tile 0 ----
    #pragma unroll
    for (int i = 0; i < 8; i++)
        ar[i] = *reinterpret_cast<const float4*>(a_ptr + (size_t)(i * 32) * Kd);
    if (TRANSB) {
        #pragma unroll
        for (int i = 0; i < 4; i++)
            br[i] = *reinterpret_cast<const float4*>(b_ptr + (size_t)(i * 32) * Kd);
    } else {
        #pragma unroll
        for (int i = 0; i < 4; i++)
            br[i] = *reinterpret_cast<const float4*>(b_ptr + (size_t)(i * 8) * N);
    }
    stage_store(0);
    __syncthreads();

    const int NT = Kd / BK;
    for (int t = 0; t < NT; t++) {
        // ---- prefetch tile t+1 into registers ----
        if (t + 1 < NT) {
            const float* ap = a_ptr + (t + 1) * BK;
            #pragma unroll
            for (int i = 0; i < 8; i++)
                ar[i] = *reinterpret_cast<const float4*>(ap + (size_t)(i * 32) * Kd);
            if (TRANSB) {
                const float* bp = b_ptr + (t + 1) * BK;
                #pragma unroll
                for (int i = 0; i < 4; i++)
                    br[i] = *reinterpret_cast<const float4*>(bp + (size_t)(i * 32) * Kd);
            } else {
                const float* bp = b_ptr + (size_t)(t + 1) * BK * N;
                #pragma unroll
                for (int i = 0; i < 4; i++)
                    br[i] = *reinterpret_cast<const float4*>(bp + (size_t)(i * 8) * N);
            }
        }

        // ---- compute from stage t&1: two k16 steps ----
        {
            const __half* As = sh + (t & 1) * STAGE_H;
            const __half* Bs = As + A_H;
            #pragma unroll
            for (int ks = 0; ks < 2; ks++) {
                const int kk = ks * 16;
                unsigned af[4][4], bf[8][2];
                #pragma unroll
                for (int mt = 0; mt < 4; mt++) {
                    int base = (wm * 64 + mt * 16 + lq) * LDKH + kk + 2 * lr;
                    af[mt][0] = *reinterpret_cast<const unsigned*>(&As[base]);
                    af[mt][1] = *reinterpret_cast<const unsigned*>(&As[base + 8 * LDKH]);
                    af[mt][2] = *reinterpret_cast<const unsigned*>(&As[base + 8]);
                    af[mt][3] = *reinterpret_cast<const unsigned*>(&As[base + 8 * LDKH + 8]);
                }
                #pragma unroll
                for (int nt = 0; nt < 8; nt++) {
                    int base = (wn * 64 + nt * 8 + lq) * LDKH + kk + 2 * lr;
                    bf[nt][0] = *reinterpret_cast<const unsigned*>(&Bs[base]);
                    bf[nt][1] = *reinterpret_cast<const unsigned*>(&Bs[base + 8]);
                }
                #pragma unroll
                for (int mt = 0; mt < 4; mt++)
                    #pragma unroll
                    for (int nt = 0; nt < 8; nt++)
                        mma_f16(acc[mt][nt],
                                af[mt][0], af[mt][1], af[mt][2], af[mt][3],
                                bf[nt][0], bf[nt][1]);
            }
        }

        // ---- cvt + store tile t+1 into the other stage ----
        if (t + 1 < NT)
            stage_store((t + 1) & 1);
        __syncthreads();
    }

    // ---- epilogue: alpha + optional bias ----
    #pragma unroll
    for (int mt = 0; mt < 4; mt++) {
        int row = by * 256 + wm * 64 + mt * 16 + lq;
        #pragma unroll
        for (int nt = 0; nt < 8; nt++) {
            int col = bx * 128 + wn * 64 + nt * 8 + 2 * lr;
            float b0 = bias ? bias[col]     : 0.0f;
            float b1 = bias ? bias[col + 1] : 0.0f;
            float2 v0, v1;
            v0.x = fmaf(acc[mt][nt][0], alpha, b0);
            v0.y = fmaf(acc[mt][nt][1], alpha, b1);
            v1.x = fmaf(acc[mt][nt][2], alpha, b0);
            v1.y = fmaf(acc[mt][nt][3], alpha, b1);
            *reinterpret_cast<float2*>(&C[(size_t)row * N + col])       = v0;
            *reinterpret_cast<float2*>(&C[(size_t)(row + 8) * N + col]) = v1;
        }
    }
}

// ---------------------------------------------------------------------------
// In-place row softmax over LK=2048 columns. One 256-thread block per row.
// ---------------------------------------------------------------------------
__global__ __launch_bounds__(256)
void softmax_rows_kernel(float* __restrict__ S)
{
    float* p = S + (size_t)blockIdx.x * LK;
    const int tid = threadIdx.x;

    float v[8];
    float m = -1e30f;
    #pragma unroll
    for (int i = 0; i < 8; i++) {
        v[i] = p[tid + i * 256];
        m = fmaxf(m, v[i]);
    }
    #pragma unroll
    for (int o = 16; o > 0; o >>= 1)
        m = fmaxf(m, __shfl_xor_sync(0xffffffffu, m, o));

    __shared__ float sm[8];
    if ((tid & 31) == 0) sm[tid >> 5] = m;
    __syncthreads();
    #pragma unroll
    for (int i = 0; i < 8; i++) m = fmaxf(m, sm[i]);

    float s = 0.0f;
    #pragma unroll
    for (int i = 0; i < 8; i++) {
        v[i] = __expf(v[i] - m);
        s += v[i];
    }
    #pragma unroll
    for (int o = 16; o > 0; o >>= 1)
        s += __shfl_xor_sync(0xffffffffu, s, o);

    __shared__ float ss[8];
    if ((tid & 31) == 0) ss[tid >> 5] = s;
    __syncthreads();
    s = 0.0f;
    #pragma unroll
    for (int i = 0; i < 8; i++) s += ss[i];

    const float inv = 1.0f / s;
    #pragma unroll
    for (int i = 0; i < 8; i++)
        p[tid + i * 256] = v[i] * inv;
}

// ---------------------------------------------------------------------------
// Host launch
// ---------------------------------------------------------------------------
extern "C" void kernel_launch(void* const* d_in, const int* in_sizes, int n_in,
                              void* d_out, int out_size)
{
    const float* Q  = (const float*)d_in[0];
    const float* K  = (const float*)d_in[1];
    const float* V  = (const float*)d_in[2];
    const float* Wk = (const float*)d_in[3];
    const float* bk = (const float*)d_in[4];
    const float* Wv = (const float*)d_in[5];
    const float* bv = (const float*)d_in[6];
    const float* Wo = (const float*)d_in[7];
    const float* bo = (const float*)d_in[8];
    float* out = (float*)d_out;

    float *Kp, *Vp, *S, *Ctx;
    cudaGetSymbolAddress((void**)&Kp,  g_Kp);
    cudaGetSymbolAddress((void**)&Vp,  g_Vp);
    cudaGetSymbolAddress((void**)&S,   g_S);
    cudaGetSymbolAddress((void**)&Ctx, g_ctx);

    cudaFuncSetAttribute(gemm_mma<true>,
        cudaFuncAttributeMaxDynamicSharedMemorySize, SMEM_BYTES);
    cudaFuncSetAttribute(gemm_mma<false>,
        cudaFuncAttributeMaxDynamicSharedMemorySize, SMEM_BYTES);

    const dim3 blk(256);

    // 1) K projection: [B*LK, D2] @ Wk^T -> [B*LK, D1]
    gemm_mma<true><<<dim3(D1 / 128, (BATCH * LK) / 256, 1), blk, SMEM_BYTES>>>(
        K, Wk, bk, Kp, D1, D2, 0, 0, 0, 1.0f);

    // 2) V projection
    gemm_mma<true><<<dim3(D1 / 128, (BATCH * LK) / 256, 1), blk, SMEM_BYTES>>>(
        V, Wv, bv, Vp, D1, D2, 0, 0, 0, 1.0f);

    // 3) scores: per-batch Q [LQ,D1] @ Kp^T [LK,D1] -> S [LQ,LK], scaled 1/32
    gemm_mma<true><<<dim3(LK / 128, LQ / 256, BATCH), blk, SMEM_BYTES>>>(
        Q, Kp, nullptr, S, LK, D1,
        (size_t)LQ * D1, (size_t)LK * D1, (size_t)LQ * LK, 0.03125f);

    // 4) softmax over last axis, one block per row
    softmax_rows_kernel<<<BATCH * LQ, blk>>>(S);

    // 5) context: per-batch P [LQ,LK] @ Vp [LK,D1] -> Ctx [LQ,D1]
    gemm_mma<false><<<dim3(D1 / 128, LQ / 256, BATCH), blk, SMEM_BYTES>>>(
        S, Vp, nullptr, Ctx, D1, LK,
        (size_t)LQ * LK, (size_t)LK * D1, (size_t)LQ * D1, 1.0f);

    // 6) output: [B*LQ, D1] @ Wo^T + bo -> out
    gemm_mma<true><<<dim3(D1 / 128, (BATCH * LQ) / 256, 1), blk, SMEM_BYTES>>>(
        Ctx, Wo, bo, out, D1, D1, 0, 0, 0, 1.0f);
}

// round 12
// speedup vs baseline: 11.0780x; 1.4351x over previous
#include <cuda_runtime.h>
#include <cuda_fp16.h>
#include <stdint.h>

// ---------------------------------------------------------------------------
// CrossAttention, fp16 mma.sync.m16n8k16, cp.async 3-stage pipeline.
// (tcgen05 unavailable: harness compiles PTX for sm_103, not sm_103a.)
//   pre-pass: Q,K,V,Wk,Wv,Wo -> fp16 copies
//   Kp  = Kh @ Wkh^T + bk      -> fp16 [B*LK][D1]
//   VpT = (Vh @ Wvh^T + bv)^T  -> fp16 [B][D1][LK]
//   S   = (Qh @ Kp^T)/32       -> fp32 [B][LQ][LK]
//   P   = softmax(S)           -> fp16
//   Ctx = P @ VpT^T            -> fp16 [B][LQ][D1]
//   O   = Ctx @ Woh^T + bo     -> fp32 (d_out)
// GEMM: CTA 128x128, BK=64 halfs, 4 warps (64x64 tiles), 2 CTAs/SM.
// ---------------------------------------------------------------------------

#define BATCH 4
#define LQ    1024
#define LK    2048
#define D1    1024
#define D2    1280

__device__ __align__(256) __half g_Qh [(size_t)BATCH * LQ * D1];
__device__ __align__(256) __half g_Kh [(size_t)BATCH * LK * D2];
__device__ __align__(256) __half g_Vh [(size_t)BATCH * LK * D2];
__device__ __align__(256) __half g_Wkh[(size_t)D1 * D2];
__device__ __align__(256) __half g_Wvh[(size_t)D1 * D2];
__device__ __align__(256) __half g_Woh[(size_t)D1 * D1];
__device__ __align__(256) __half g_Kp [(size_t)BATCH * LK * D1];
__device__ __align__(256) __half g_VpT[(size_t)BATCH * D1 * LK];
__device__ __align__(256) float  g_S  [(size_t)BATCH * LQ * LK];
__device__ __align__(256) __half g_P  [(size_t)BATCH * LQ * LK];
__device__ __align__(256) __half g_ctx[(size_t)BATCH * LQ * D1];

#define STAGE_BYTES 32768          // A 128x64 halfs (16KB) + B 128x64 (16KB)
#define NSTAGE 3
#define SMEM_BYTES (NSTAGE * STAGE_BYTES)   // 98304; 2 CTAs/SM = 192KB

static __device__ __forceinline__ uint32_t smem_u32(const void* p) {
    uint32_t a;
    asm("{ .reg .u64 t; cvta.to.shared.u64 t, %1; cvt.u32.u64 %0, t; }"
        : "=r"(a) : "l"(p));
    return a;
}
static __device__ __forceinline__ void cpasync16(uint32_t dst, const void* src) {
    asm volatile("cp.async.cg.shared.global [%0], [%1], 16;"
                 :: "r"(dst), "l"(src) : "memory");
}
#define CP_COMMIT() asm volatile("cp.async.commit_group;" ::: "memory")
#define CP_WAIT1()  asm volatile("cp.async.wait_group 1;"  ::: "memory")

static __device__ __forceinline__ void mma_f16(float c[4],
                                               unsigned a0, unsigned a1,
                                               unsigned a2, unsigned a3,
                                               unsigned b0, unsigned b1) {
    asm volatile(
        "mma.sync.aligned.m16n8k16.row.col.f32.f16.f16.f32 "
        "{%0,%1,%2,%3}, {%4,%5,%6,%7}, {%8,%9}, {%0,%1,%2,%3};"
        : "+f"(c[0]), "+f"(c[1]), "+f"(c[2]), "+f"(c[3])
        : "r"(a0), "r"(a1), "r"(a2), "r"(a3), "r"(b0), "r"(b1));
}

// ---------------------------------------------------------------------------
// fp16 GEMM: C[m,n] = alpha * sum_k A[m,k]*B[n,k] (+bias[n]).
// A,B fp16 K-major. Grid (N/128, M/128, Z). Kd % 64 == 0.
// Smem layout per stage: 128-byte rows, 16B chunks XOR-swizzled by row&7
// -> cp.async dst 16B aligned, fragment LDS.32 conflict-free.
// ---------------------------------------------------------------------------
template<bool OUT_HALF, bool OUT_TRANS>
__global__ __launch_bounds__(128, 2)
void gemm_f16(const __half* __restrict__ Ap, const __half* __restrict__ Bp,
              const float* __restrict__ bias, void* __restrict__ Cp,
              int ldC, int Kd, size_t sA, size_t sB, size_t sC, float alpha)
{
    extern __shared__ __align__(16) char shp[];

    const int tid  = threadIdx.x;
    const int warp = tid >> 5, lane = tid & 31;
    const int bx = blockIdx.x, by = blockIdx.y, bz = blockIdx.z;
    const int wm = warp >> 1, wn = warp & 1;     // 2x2 warp grid, 64x64 tiles
    const int lq = lane >> 2, lr = lane & 3;

    const __half* Ab = Ap + bz * sA + (size_t)(by * 128) * Kd;
    const __half* Bb = Bp + bz * sB + (size_t)(bx * 128) * Kd;

    // staging: thread -> row base r0 (8 rows, stride 16), chunk kc (16B)
    const int r0 = tid >> 3, kc = tid & 7;
    const uint32_t swoff = (uint32_t)((kc ^ (r0 & 7)) << 4);
    const uint32_t sb = smem_u32(shp);

    auto issue = [&](int slot, int k0) {
        const uint32_t ab = sb + slot * STAGE_BYTES;
        const uint32_t bb = ab + STAGE_BYTES / 2;
        #pragma unroll
        for (int i = 0; i < 8; i++) {
            const int row = r0 + 16 * i;
            cpasync16(ab + row * 128 + swoff, Ab + (size_t)row * Kd + k0 + kc * 8);
        }
        #pragma unroll
        for (int i = 0; i < 8; i++) {
            const int row = r0 + 16 * i;
            cpasync16(bb + row * 128 + swoff, Bb + (size_t)row * Kd + k0 + kc * 8);
        }
        CP_COMMIT();
    };

    float acc[4][8][4];
    #pragma unroll
    for (int mt = 0; mt < 4; mt++)
        #pragma unroll
        for (int nt = 0; nt < 8; nt++)
            #pragma unroll
            for (int i = 0; i < 4; i++)
                acc[mt][nt][i] = 0.0f;

    issue(0, 0);
    issue(1, 64);

    const int NT = Kd >> 6;
    for (int t = 0; t < NT; t++) {
        CP_WAIT1();             // oldest group (stage t) landed
        __syncthreads();
        if (t + 2 < NT) issue((t + 2) % NSTAGE, (t + 2) * 64);
        else            CP_COMMIT();     // keep group count uniform

        const char* As = shp + (t % NSTAGE) * STAGE_BYTES;
        const char* Bs = As + STAGE_BYTES / 2;

        #pragma unroll
        for (int ks = 0; ks < 4; ks++) {
            const int c0 = 2 * ks;       // 16B-chunk index of kk=16*ks
            const uint32_t x0 = (uint32_t)(((c0    ) ^ lq) << 4) + 4 * lr;
            const uint32_t x1 = (uint32_t)(((c0 + 1) ^ lq) << 4) + 4 * lr;
            unsigned af[4][4], bf[8][2];
            #pragma unroll
            for (int mt = 0; mt < 4; mt++) {
                const int mb = (wm * 64 + mt * 16 + lq) * 128;
                af[mt][0] = *(const unsigned*)(As + mb + x0);
                af[mt][1] = *(const unsigned*)(As + mb + 1024 + x0);
                af[mt][2] = *(const unsigned*)(As + mb + x1);
                af[mt][3] = *(const unsigned*)(As + mb + 1024 + x1);
            }
            #pragma unroll
            for (int nt = 0; nt < 8; nt++) {
                const int nb = (wn * 64 + nt * 8 + lq) * 128;
                bf[nt][0] = *(const unsigned*)(Bs + nb + x0);
                bf[nt][1] = *(const unsigned*)(Bs + nb + x1);
            }
            #pragma unroll
            for (int mt = 0; mt < 4; mt++)
                #pragma unroll
                for (int nt = 0; nt < 8; nt++)
                    mma_f16(acc[mt][nt],
                            af[mt][0], af[mt][1], af[mt][2], af[mt][3],
                            bf[nt][0], bf[nt][1]);
        }
    }

    if (OUT_TRANS) {
        // write tile transposed (rows=lk, cols=d) -> out[d][lk], via smem fp32
        __syncthreads();
        float* sme = reinterpret_cast<float*>(shp);
        #pragma unroll
        for (int mt = 0; mt < 4; mt++) {
            const int r = wm * 64 + mt * 16 + lq;
            #pragma unroll
            for (int nt = 0; nt < 8; nt++) {
                const int c = wn * 64 + nt * 8 + 2 * lr;
                sme[r * 129 + c]           = acc[mt][nt][0];
                sme[r * 129 + c + 1]       = acc[mt][nt][1];
                sme[(r + 8) * 129 + c]     = acc[mt][nt][2];
                sme[(r + 8) * 129 + c + 1] = acc[mt][nt][3];
            }
        }
        __syncthreads();
        __half* Ch = (__half*)Cp;
        const int b   = (by * 128) / LK;
        const int lkb = (by * 128) % LK;
        #pragma unroll 4
        for (int it = 0; it < 32; it++) {
            const int idx = it * 128 + tid;
            const int c  = idx >> 5;          // local d col
            const int f4 = (idx & 31) * 4;    // local lk
            const float bb = bias ? __ldg(&bias[bx * 128 + c]) : 0.0f;
            float v0 = fmaf(sme[(f4 + 0) * 129 + c], alpha, bb);
            float v1 = fmaf(sme[(f4 + 1) * 129 + c], alpha, bb);
            float v2 = fmaf(sme[(f4 + 2) * 129 + c], alpha, bb);
            float v3 = fmaf(sme[(f4 + 3) * 129 + c], alpha, bb);
            __half2 h0 = __floats2half2_rn(v0, v1);
            __half2 h1 = __floats2half2_rn(v2, v3);
            uint2 w; w.x = *(uint32_t*)&h0; w.y = *(uint32_t*)&h1;
            *reinterpret_cast<uint2*>(
                Ch + (size_t)b * D1 * LK + (size_t)(bx * 128 + c) * LK + lkb + f4) = w;
        }
    } else {
        #pragma unroll
        for (int mt = 0; mt < 4; mt++) {
            const int row = by * 128 + wm * 64 + mt * 16 + lq;
            #pragma unroll
            for (int nt = 0; nt < 8; nt++) {
                const int col = bx * 128 + wn * 64 + nt * 8 + 2 * lr;
                const float b0 = bias ? __ldg(&bias[col])     : 0.0f;
                const float b1 = bias ? __ldg(&bias[col + 1]) : 0.0f;
                const float v0 = fmaf(acc[mt][nt][0], alpha, b0);
                const float v1 = fmaf(acc[mt][nt][1], alpha, b1);
                const float v2 = fmaf(acc[mt][nt][2], alpha, b0);
                const float v3 = fmaf(acc[mt][nt][3], alpha, b1);
                const size_t o0 = (size_t)bz * sC + (size_t)row * ldC + col;
                const size_t o1 = (size_t)bz * sC + (size_t)(row + 8) * ldC + col;
                if (OUT_HALF) {
                    *(__half2*)((__half*)Cp + o0) = __floats2half2_rn(v0, v1);
                    *(__half2*)((__half*)Cp + o1) = __floats2half2_rn(v2, v3);
                } else {
                    *(float2*)((float*)Cp + o0) = make_float2(v0, v1);
                    *(float2*)((float*)Cp + o1) = make_float2(v2, v3);
                }
            }
        }
    }
}

// ---------------------------------------------------------------------------
// fp32 -> fp16 bulk convert (n % 8 == 0)
// ---------------------------------------------------------------------------
__global__ __launch_bounds__(256)
void cvt_f2h(const float* __restrict__ s, __half* __restrict__ d, int n)
{
    const int i = (blockIdx.x * 256 + threadIdx.x) * 8;
    if (i >= n) return;
    float4 a = *reinterpret_cast<const float4*>(s + i);
    float4 b = *reinterpret_cast<const float4*>(s + i + 4);
    __half2 h0 = __floats2half2_rn(a.x, a.y);
    __half2 h1 = __floats2half2_rn(a.z, a.w);
    __half2 h2 = __floats2half2_rn(b.x, b.y);
    __half2 h3 = __floats2half2_rn(b.z, b.w);
    uint4 u;
    u.x = *(uint32_t*)&h0; u.y = *(uint32_t*)&h1;
    u.z = *(uint32_t*)&h2; u.w = *(uint32_t*)&h3;
    *reinterpret_cast<uint4*>(d + i) = u;
}

// ---------------------------------------------------------------------------
// Row softmax: fp32 in, fp16 out. One 256-thread block per row of LK=2048.
// ---------------------------------------------------------------------------
__global__ __launch_bounds__(256)
void softmax_rows_kernel(const float* __restrict__ S, __half* __restrict__ P)
{
    const float* p = S + (size_t)blockIdx.x * LK;
    __half* q = P + (size_t)blockIdx.x * LK;
    const int tid = threadIdx.x;

    float v[8];
    float m = -1e30f;
    #pragma unroll
    for (int i = 0; i < 8; i++) {
        v[i] = p[tid + i * 256];
        m = fmaxf(m, v[i]);
    }
    #pragma unroll
    for (int o = 16; o > 0; o >>= 1)
        m = fmaxf(m, __shfl_xor_sync(0xffffffffu, m, o));
    __shared__ float sm[8];
    if ((tid & 31) == 0) sm[tid >> 5] = m;
    __syncthreads();
    #pragma unroll
    for (int i = 0; i < 8; i++) m = fmaxf(m, sm[i]);

    float s = 0.0f;
    #pragma unroll
    for (int i = 0; i < 8; i++) { v[i] = __expf(v[i] - m); s += v[i]; }
    #pragma unroll
    for (int o = 16; o > 0; o >>= 1)
        s += __shfl_xor_sync(0xffffffffu, s, o);
    __shared__ float ss[8];
    if ((tid & 31) == 0) ss[tid >> 5] = s;
    __syncthreads();
    s = 0.0f;
    #pragma unroll
    for (int i = 0; i < 8; i++) s += ss[i];

    const float inv = 1.0f / s;
    #pragma unroll
    for (int i = 0; i < 8; i++)
        q[tid + i * 256] = __float2half_rn(v[i] * inv);
}

// ---------------------------------------------------------------------------
// Host launch
// ---------------------------------------------------------------------------
extern "C" void kernel_launch(void* const* d_in, const int* in_sizes, int n_in,
                              void* d_out, int out_size)
{
    const float* Q  = (const float*)d_in[0];
    const float* K  = (const float*)d_in[1];
    const float* V  = (const float*)d_in[2];
    const float* Wk = (const float*)d_in[3];
    const float* bk = (const float*)d_in[4];
    const float* Wv = (const float*)d_in[5];
    const float* bv = (const float*)d_in[6];
    const float* Wo = (const float*)d_in[7];
    const float* bo = (const float*)d_in[8];
    float* out = (float*)d_out;

    void *Qh, *Kh, *Vh, *Wkh, *Wvh, *Woh, *Kp, *VpT, *S, *P, *Ctx;
    cudaGetSymbolAddress(&Qh,  g_Qh);  cudaGetSymbolAddress(&Kh,  g_Kh);
    cudaGetSymbolAddress(&Vh,  g_Vh);  cudaGetSymbolAddress(&Wkh, g_Wkh);
    cudaGetSymbolAddress(&Wvh, g_Wvh); cudaGetSymbolAddress(&Woh, g_Woh);
    cudaGetSymbolAddress(&Kp,  g_Kp);  cudaGetSymbolAddress(&VpT, g_VpT);
    cudaGetSymbolAddress(&S,   g_S);   cudaGetSymbolAddress(&P,   g_P);
    cudaGetSymbolAddress(&Ctx, g_ctx);

    cudaFuncSetAttribute(gemm_f16<true,false>,
        cudaFuncAttributeMaxDynamicSharedMemorySize, SMEM_BYTES);
    cudaFuncSetAttribute(gemm_f16<true,true>,
        cudaFuncAttributeMaxDynamicSharedMemorySize, SMEM_BYTES);
    cudaFuncSetAttribute(gemm_f16<false,false>,
        cudaFuncAttributeMaxDynamicSharedMemorySize, SMEM_BYTES);

    // ---- fp32 -> fp16 pre-pass ----
    auto cvt = [&](const float* src, void* dst, size_t n) {
        cvt_f2h<<<(unsigned)(n / 8 / 256), 256>>>(src, (__half*)dst, (int)n);
    };
    cvt(Q,  Qh,  (size_t)BATCH * LQ * D1);
    cvt(K,  Kh,  (size_t)BATCH * LK * D2);
    cvt(V,  Vh,  (size_t)BATCH * LK * D2);
    cvt(Wk, Wkh, (size_t)D1 * D2);
    cvt(Wv, Wvh, (size_t)D1 * D2);
    cvt(Wo, Woh, (size_t)D1 * D1);

    const dim3 blk(128);

    // 1) Kp = Kh @ Wkh^T + bk -> fp16 [B*LK][D1]
    gemm_f16<true,false><<<dim3(D1/128, (BATCH*LK)/128, 1), blk, SMEM_BYTES>>>(
        (const __half*)Kh, (const __half*)Wkh, bk, Kp, D1, D2, 0, 0, 0, 1.0f);

    // 2) VpT = (Vh @ Wvh^T + bv)^T -> fp16 [B][D1][LK]
    gemm_f16<true,true><<<dim3(D1/128, (BATCH*LK)/128, 1), blk, SMEM_BYTES>>>(
        (const __half*)Vh, (const __half*)Wvh, bv, VpT, LK, D2, 0, 0, 0, 1.0f);

    // 3) S = (Qh @ Kp^T)/32 -> fp32, per batch
    gemm_f16<false,false><<<dim3(LK/128, LQ/128, BATCH), blk, SMEM_BYTES>>>(
        (const __half*)Qh, (const __half*)Kp, nullptr, S, LK, D1,
        (size_t)LQ*D1, (size_t)LK*D1, (size_t)LQ*LK, 0.03125f);

    // 4) P = softmax(S) -> fp16
    softmax_rows_kernel<<<BATCH*LQ, 256>>>((const float*)S, (__half*)P);

    // 5) Ctx = P @ VpT^T -> fp16, per batch
    gemm_f16<true,false><<<dim3(D1/128, LQ/128, BATCH), blk, SMEM_BYTES>>>(
        (const __half*)P, (const __half*)VpT, nullptr, Ctx, D1, LK,
        (size_t)LQ*LK, (size_t)D1*LK, (size_t)LQ*D1, 1.0f);

    // 6) O = Ctx @ Woh^T + bo -> fp32 out
    gemm_f16<false,false><<<dim3(D1/128, (BATCH*LQ)/128, 1), blk, SMEM_BYTES>>>(
        (const __half*)Ctx, (const __half*)Woh, bo, out, D1, D1, 0, 0, 0, 1.0f);
}

// round 14
// speedup vs baseline: 12.1523x; 1.0970x over previous
#include <cuda_runtime.h>
#include <cuda_fp16.h>
#include <stdint.h>

// ---------------------------------------------------------------------------
// CrossAttention, fp16 mma.sync.m16n8k16, cp.async 3-stage pipeline,
// re-associated to minimize MACs (43 -> 36.5 GMAC):
//   Qk  = Qh @ Wk            (bk dropped: softmax-invariant)   fp16 [B,LQ,D2]
//   S   = (Qk @ Kh^T)/32                                       fp32 [B,LQ,LK]
//   P   = softmax(S)                                           fp16
//   T   = P @ Vh                                               fp16 [B,LQ,D2]
//   Ctx = T @ Wv^T + bv      (exact: P rows sum to 1)          fp16 [B,LQ,D1]
//   O   = Ctx @ Wo^T + bo                                      fp32 (d_out)
// Pre-pass: plain cvt fp32->fp16 of Q,K,Wv,Wo; transpose-cvt of Wk, V.
// GEMM: CTA 128x128, BK=64 halfs, 4 warps (64x64 tiles), 2 CTAs/SM.
// ---------------------------------------------------------------------------

#define BATCH 4
#define LQ    1024
#define LK    2048
#define D1    1024
#define D2    1280

__device__ __align__(256) __half g_Qh [(size_t)BATCH * LQ * D1];
__device__ __align__(256) __half g_Kh [(size_t)BATCH * LK * D2];
__device__ __align__(256) __half g_WkT[(size_t)D2 * D1];          // Wk^T
__device__ __align__(256) __half g_VhT[(size_t)BATCH * D2 * LK];  // V^T per batch
__device__ __align__(256) __half g_Wvh[(size_t)D1 * D2];
__device__ __align__(256) __half g_Woh[(size_t)D1 * D1];
__device__ __align__(256) __half g_Qk [(size_t)BATCH * LQ * D2];
__device__ __align__(256) float  g_S  [(size_t)BATCH * LQ * LK];
__device__ __align__(256) __half g_P  [(size_t)BATCH * LQ * LK];
__device__ __align__(256) __half g_T  [(size_t)BATCH * LQ * D2];
__device__ __align__(256) __half g_Ctx[(size_t)BATCH * LQ * D1];

#define STAGE_BYTES 32768          // A 128x64 halfs (16KB) + B 128x64 (16KB)
#define NSTAGE 3
#define SMEM_BYTES (NSTAGE * STAGE_BYTES)   // 98304; 2 CTAs/SM

static __device__ __forceinline__ uint32_t smem_u32(const void* p) {
    uint32_t a;
    asm("{ .reg .u64 t; cvta.to.shared.u64 t, %1; cvt.u32.u64 %0, t; }"
        : "=r"(a) : "l"(p));
    return a;
}
static __device__ __forceinline__ void cpasync16(uint32_t dst, const void* src) {
    asm volatile("cp.async.cg.shared.global [%0], [%1], 16;"
                 :: "r"(dst), "l"(src) : "memory");
}
#define CP_COMMIT() asm volatile("cp.async.commit_group;" ::: "memory")
#define CP_WAIT1()  asm volatile("cp.async.wait_group 1;"  ::: "memory")

static __device__ __forceinline__ void mma_f16(float c[4],
                                               unsigned a0, unsigned a1,
                                               unsigned a2, unsigned a3,
                                               unsigned b0, unsigned b1) {
    asm volatile(
        "mma.sync.aligned.m16n8k16.row.col.f32.f16.f16.f32 "
        "{%0,%1,%2,%3}, {%4,%5,%6,%7}, {%8,%9}, {%0,%1,%2,%3};"
        : "+f"(c[0]), "+f"(c[1]), "+f"(c[2]), "+f"(c[3])
        : "r"(a0), "r"(a1), "r"(a2), "r"(a3), "r"(b0), "r"(b1));
}

// ---------------------------------------------------------------------------
// fp16 GEMM: C[m,n] = alpha * sum_k A[m,k]*B[n,k] (+bias[n]).
// A,B fp16 K-major. Grid (N/128, M/128, Z). Kd % 64 == 0.
// ---------------------------------------------------------------------------
template<bool OUT_HALF>
__global__ __launch_bounds__(128, 2)
void gemm_f16(const __half* __restrict__ Ap, const __half* __restrict__ Bp,
              const float* __restrict__ bias, void* __restrict__ Cp,
              int ldC, int Kd, size_t sA, size_t sB, size_t sC, float alpha)
{
    extern __shared__ __align__(16) char shp[];

    const int tid  = threadIdx.x;
    const int warp = tid >> 5, lane = tid & 31;
    const int bx = blockIdx.x, by = blockIdx.y, bz = blockIdx.z;
    const int wm = warp >> 1, wn = warp & 1;     // 2x2 warp grid, 64x64 tiles
    const int lq = lane >> 2, lr = lane & 3;

    const __half* Ab = Ap + bz * sA + (size_t)(by * 128) * Kd;
    const __half* Bb = Bp + bz * sB + (size_t)(bx * 128) * Kd;

    const int r0 = tid >> 3, kc = tid & 7;
    const uint32_t swoff = (uint32_t)((kc ^ (r0 & 7)) << 4);
    const uint32_t sb = smem_u32(shp);

    auto issue = [&](int slot, int k0) {
        const uint32_t ab = sb + slot * STAGE_BYTES;
        const uint32_t bb = ab + STAGE_BYTES / 2;
        #pragma unroll
        for (int i = 0; i < 8; i++) {
            const int row = r0 + 16 * i;
            cpasync16(ab + row * 128 + swoff, Ab + (size_t)row * Kd + k0 + kc * 8);
        }
        #pragma unroll
        for (int i = 0; i < 8; i++) {
            const int row = r0 + 16 * i;
            cpasync16(bb + row * 128 + swoff, Bb + (size_t)row * Kd + k0 + kc * 8);
        }
        CP_COMMIT();
    };

    float acc[4][8][4];
    #pragma unroll
    for (int mt = 0; mt < 4; mt++)
        #pragma unroll
        for (int nt = 0; nt < 8; nt++)
            #pragma unroll
            for (int i = 0; i < 4; i++)
                acc[mt][nt][i] = 0.0f;

    issue(0, 0);
    issue(1, 64);

    const int NT = Kd >> 6;
    for (int t = 0; t < NT; t++) {
        CP_WAIT1();
        __syncthreads();
        if (t + 2 < NT) issue((t + 2) % NSTAGE, (t + 2) * 64);
        else            CP_COMMIT();

        const char* As = shp + (t % NSTAGE) * STAGE_BYTES;
        const char* Bs = As + STAGE_BYTES / 2;

        #pragma unroll
        for (int ks = 0; ks < 4; ks++) {
            const int c0 = 2 * ks;
            const uint32_t x0 = (uint32_t)(((c0    ) ^ lq) << 4) + 4 * lr;
            const uint32_t x1 = (uint32_t)(((c0 + 1) ^ lq) << 4) + 4 * lr;
            unsigned af[4][4], bf[8][2];
            #pragma unroll
            for (int mt = 0; mt < 4; mt++) {
                const int mb = (wm * 64 + mt * 16 + lq) * 128;
                af[mt][0] = *(const unsigned*)(As + mb + x0);
                af[mt][1] = *(const unsigned*)(As + mb + 1024 + x0);
                af[mt][2] = *(const unsigned*)(As + mb + x1);
                af[mt][3] = *(const unsigned*)(As + mb + 1024 + x1);
            }
            #pragma unroll
            for (int nt = 0; nt < 8; nt++) {
                const int nb = (wn * 64 + nt * 8 + lq) * 128;
                bf[nt][0] = *(const unsigned*)(Bs + nb + x0);
                bf[nt][1] = *(const unsigned*)(Bs + nb + x1);
            }
            #pragma unroll
            for (int mt = 0; mt < 4; mt++)
                #pragma unroll
                for (int nt = 0; nt < 8; nt++)
                    mma_f16(acc[mt][nt],
                            af[mt][0], af[mt][1], af[mt][2], af[mt][3],
                            bf[nt][0], bf[nt][1]);
        }
    }

    #pragma unroll
    for (int mt = 0; mt < 4; mt++) {
        const int row = by * 128 + wm * 64 + mt * 16 + lq;
        #pragma unroll
        for (int nt = 0; nt < 8; nt++) {
            const int col = bx * 128 + wn * 64 + nt * 8 + 2 * lr;
            const float b0 = bias ? __ldg(&bias[col])     : 0.0f;
            const float b1 = bias ? __ldg(&bias[col + 1]) : 0.0f;
            const float v0 = fmaf(acc[mt][nt][0], alpha, b0);
            const float v1 = fmaf(acc[mt][nt][1], alpha, b1);
            const float v2 = fmaf(acc[mt][nt][2], alpha, b0);
            const float v3 = fmaf(acc[mt][nt][3], alpha, b1);
            const size_t o0 = (size_t)bz * sC + (size_t)row * ldC + col;
            const size_t o1 = (size_t)bz * sC + (size_t)(row + 8) * ldC + col;
            if (OUT_HALF) {
                *(__half2*)((__half*)Cp + o0) = __floats2half2_rn(v0, v1);
                *(__half2*)((__half*)Cp + o1) = __floats2half2_rn(v2, v3);
            } else {
                *(float2*)((float*)Cp + o0) = make_float2(v0, v1);
                *(float2*)((float*)Cp + o1) = make_float2(v2, v3);
            }
        }
    }
}

// ---------------------------------------------------------------------------
// fp32 -> fp16 bulk convert (n % 2048 == 0)
// ---------------------------------------------------------------------------
__global__ __launch_bounds__(256)
void cvt_f2h(const float* __restrict__ s, __half* __restrict__ d, int n)
{
    const int i = (blockIdx.x * 256 + threadIdx.x) * 8;
    if (i >= n) return;
    float4 a = *reinterpret_cast<const float4*>(s + i);
    float4 b = *reinterpret_cast<const float4*>(s + i + 4);
    __half2 h0 = __floats2half2_rn(a.x, a.y);
    __half2 h1 = __floats2half2_rn(a.z, a.w);
    __half2 h2 = __floats2half2_rn(b.x, b.y);
    __half2 h3 = __floats2half2_rn(b.z, b.w);
    uint4 u;
    u.x = *(uint32_t*)&h0; u.y = *(uint32_t*)&h1;
    u.z = *(uint32_t*)&h2; u.w = *(uint32_t*)&h3;
    *reinterpret_cast<uint4*>(d + i) = u;
}

// ---------------------------------------------------------------------------
// fp32 -> fp16 transpose-convert. src [R, C] -> dst [C, R], per batch z.
// 32x32 tiles, block (32, 8). Requires R%32==0, C%32==0.
// ---------------------------------------------------------------------------
__global__ __launch_bounds__(256)
void cvt_f2h_T(const float* __restrict__ src, __half* __restrict__ dst,
               int R, int C)
{
    __shared__ float t[32][33];
    const int c0 = blockIdx.x * 32, r0 = blockIdx.y * 32;
    const size_t sb = (size_t)blockIdx.z * R * C;
    const int tx = threadIdx.x, ty = threadIdx.y;

    #pragma unroll
    for (int i = 0; i < 4; i++)
        t[ty + 8 * i][tx] = src[sb + (size_t)(r0 + ty + 8 * i) * C + c0 + tx];
    __syncthreads();
    #pragma unroll
    for (int i = 0; i < 4; i++)
        dst[sb + (size_t)(c0 + ty + 8 * i) * R + r0 + tx] =
            __float2half_rn(t[tx][ty + 8 * i]);
}

// ---------------------------------------------------------------------------
// Row softmax: fp32 in, fp16 out. One 256-thread block per row of LK=2048.
// ---------------------------------------------------------------------------
__global__ __launch_bounds__(256)
void softmax_rows_kernel(const float* __restrict__ S, __half* __restrict__ P)
{
    const float* p = S + (size_t)blockIdx.x * LK;
    __half* q = P + (size_t)blockIdx.x * LK;
    const int tid = threadIdx.x;

    float v[8];
    float m = -1e30f;
    #pragma unroll
    for (int i = 0; i < 8; i++) {
        v[i] = p[tid + i * 256];
        m = fmaxf(m, v[i]);
    }
    #pragma unroll
    for (int o = 16; o > 0; o >>= 1)
        m = fmaxf(m, __shfl_xor_sync(0xffffffffu, m, o));
    __shared__ float sm[8];
    if ((tid & 31) == 0) sm[tid >> 5] = m;
    __syncthreads();
    #pragma unroll
    for (int i = 0; i < 8; i++) m = fmaxf(m, sm[i]);

    float s = 0.0f;
    #pragma unroll
    for (int i = 0; i < 8; i++) { v[i] = __expf(v[i] - m); s += v[i]; }
    #pragma unroll
    for (int o = 16; o > 0; o >>= 1)
        s += __shfl_xor_sync(0xffffffffu, s, o);
    __shared__ float ss[8];
    if ((tid & 31) == 0) ss[tid >> 5] = s;
    __syncthreads();
    s = 0.0f;
    #pragma unroll
    for (int i = 0; i < 8; i++) s += ss[i];

    const float inv = 1.0f / s;
    #pragma unroll
    for (int i = 0; i < 8; i++)
        q[tid + i * 256] = __float2half_rn(v[i] * inv);
}

// ---------------------------------------------------------------------------
// Host launch
// ---------------------------------------------------------------------------
extern "C" void kernel_launch(void* const* d_in, const int* in_sizes, int n_in,
                              void* d_out, int out_size)
{
    const float* Q  = (const float*)d_in[0];
    const float* K  = (const float*)d_in[1];
    const float* V  = (const float*)d_in[2];
    const float* Wk = (const float*)d_in[3];
    const float* Wv = (const float*)d_in[5];
    const float* bv = (const float*)d_in[6];
    const float* Wo = (const float*)d_in[7];
    const float* bo = (const float*)d_in[8];
    float* out = (float*)d_out;

    void *Qh, *Kh, *WkT, *VhT, *Wvh, *Woh, *Qk, *S, *P, *T, *Ctx;
    cudaGetSymbolAddress(&Qh,  g_Qh);  cudaGetSymbolAddress(&Kh,  g_Kh);
    cudaGetSymbolAddress(&WkT, g_WkT); cudaGetSymbolAddress(&VhT, g_VhT);
    cudaGetSymbolAddress(&Wvh, g_Wvh); cudaGetSymbolAddress(&Woh, g_Woh);
    cudaGetSymbolAddress(&Qk,  g_Qk);  cudaGetSymbolAddress(&S,   g_S);
    cudaGetSymbolAddress(&P,   g_P);   cudaGetSymbolAddress(&T,   g_T);
    cudaGetSymbolAddress(&Ctx, g_Ctx);

    cudaFuncSetAttribute(gemm_f16<true>,
        cudaFuncAttributeMaxDynamicSharedMemorySize, SMEM_BYTES);
    cudaFuncSetAttribute(gemm_f16<false>,
        cudaFuncAttributeMaxDynamicSharedMemorySize, SMEM_BYTES);

    // ---- fp32 -> fp16 pre-pass ----
    auto cvt = [&](const float* src, void* dst, size_t n) {
        cvt_f2h<<<(unsigned)(n / 8 / 256), 256>>>(src, (__half*)dst, (int)n);
    };
    cvt(Q,  Qh,  (size_t)BATCH * LQ * D1);
    cvt(K,  Kh,  (size_t)BATCH * LK * D2);
    cvt(Wv, Wvh, (size_t)D1 * D2);
    cvt(Wo, Woh, (size_t)D1 * D1);
    // Wk [D1,D2] -> WkT [D2,D1];  V [B][LK,D2] -> VhT [B][D2,LK]
    cvt_f2h_T<<<dim3(D2/32, D1/32, 1),     dim3(32,8)>>>(Wk, (__half*)WkT, D1, D2);
    cvt_f2h_T<<<dim3(D2/32, LK/32, BATCH), dim3(32,8)>>>(V,  (__half*)VhT, LK, D2);

    const dim3 blk(128);

    // 1) Qk = Qh @ WkT^T  (= Q @ Wk; bk dropped, softmax-invariant)
    gemm_f16<true><<<dim3(D2/128, (BATCH*LQ)/128, 1), blk, SMEM_BYTES>>>(
        (const __half*)Qh, (const __half*)WkT, nullptr, Qk, D2, D1, 0, 0, 0, 1.0f);

    // 2) S = (Qk @ Kh^T)/32 -> fp32, per batch
    gemm_f16<false><<<dim3(LK/128, LQ/128, BATCH), blk, SMEM_BYTES>>>(
        (const __half*)Qk, (const __half*)Kh, nullptr, S, LK, D2,
        (size_t)LQ*D2, (size_t)LK*D2, (size_t)LQ*LK, 0.03125f);

    // 3) P = softmax(S) -> fp16
    softmax_rows_kernel<<<BATCH*LQ, 256>>>((const float*)S, (__half*)P);

    // 4) T = P @ VhT^T (= P @ V) -> fp16, per batch
    gemm_f16<true><<<dim3(D2/128, LQ/128, BATCH), blk, SMEM_BYTES>>>(
        (const __half*)P, (const __half*)VhT, nullptr, T, D2, LK,
        (size_t)LQ*LK, (size_t)D2*LK, (size_t)LQ*D2, 1.0f);

    // 5) Ctx = T @ Wvh^T + bv -> fp16  (exact: P rows sum to 1)
    gemm_f16<true><<<dim3(D1/128, (BATCH*LQ)/128, 1), blk, SMEM_BYTES>>>(
        (const __half*)T, (const __half*)Wvh, bv, Ctx, D1, D2, 0, 0, 0, 1.0f);

    // 6) O = Ctx @ Woh^T + bo -> fp32 out
    gemm_f16<false><<<dim3(D1/128, (BATCH*LQ)/128, 1), blk, SMEM_BYTES>>>(
        (const __half*)Ctx, (const __half*)Woh, bo, out, D1, D1, 0, 0, 0, 1.0f);
}

// round 15
// speedup vs baseline: 12.3874x; 1.0193x over previous
#include <cuda_runtime.h>
#include <cuda_fp16.h>
#include <stdint.h>

// ---------------------------------------------------------------------------
// CrossAttention, fp16 mma.sync.m16n8k16, cp.async 3-stage pipeline,
// re-associated twice (36.4 -> 33.5 GMAC):
//   Qk  = Qh @ Wk              (bk dropped: softmax-invariant)  fp16 [B,LQ,D2]
//   S   = (Qk @ Kh^T)/32                                        fp32 [B,LQ,LK]
//   P   = softmax(S)                                            fp16
//   T   = P @ Vh                                                fp16 [B,LQ,D2]
//   Wov = Wo @ Wv   (precomputed once)                          fp16 [D1,D2]
//   O   = T @ Wov^T + (Wo.bv + bo)   (exact linearity fold)     fp32 (d_out)
// Pre-pass: plain cvt of Q,K,Wo; transpose-cvt of Wk, V, Wv.
// GEMM: CTA 128x128, BK=64 halfs, 4 warps (64x64 tiles), 2 CTAs/SM.
// ---------------------------------------------------------------------------

#define BATCH 4
#define LQ    1024
#define LK    2048
#define D1    1024
#define D2    1280

__device__ __align__(256) __half g_Qh [(size_t)BATCH * LQ * D1];
__device__ __align__(256) __half g_Kh [(size_t)BATCH * LK * D2];
__device__ __align__(256) __half g_WkT[(size_t)D2 * D1];          // Wk^T
__device__ __align__(256) __half g_VhT[(size_t)BATCH * D2 * LK];  // V^T per batch
__device__ __align__(256) __half g_WvT[(size_t)D2 * D1];          // Wv^T
__device__ __align__(256) __half g_Woh[(size_t)D1 * D1];
__device__ __align__(256) __half g_Wov[(size_t)D1 * D2];          // Wo @ Wv
__device__ __align__(256) float  g_bo2[D1];                       // Wo.bv + bo
__device__ __align__(256) __half g_Qk [(size_t)BATCH * LQ * D2];
__device__ __align__(256) float  g_S  [(size_t)BATCH * LQ * LK];
__device__ __align__(256) __half g_P  [(size_t)BATCH * LQ * LK];
__device__ __align__(256) __half g_T  [(size_t)BATCH * LQ * D2];

#define STAGE_BYTES 32768          // A 128x64 halfs (16KB) + B 128x64 (16KB)
#define NSTAGE 3
#define SMEM_BYTES (NSTAGE * STAGE_BYTES)   // 98304; 2 CTAs/SM

static __device__ __forceinline__ uint32_t smem_u32(const void* p) {
    uint32_t a;
    asm("{ .reg .u64 t; cvta.to.shared.u64 t, %1; cvt.u32.u64 %0, t; }"
        : "=r"(a) : "l"(p));
    return a;
}
static __device__ __forceinline__ void cpasync16(uint32_t dst, const void* src) {
    asm volatile("cp.async.cg.shared.global [%0], [%1], 16;"
                 :: "r"(dst), "l"(src) : "memory");
}
#define CP_COMMIT() asm volatile("cp.async.commit_group;" ::: "memory")
#define CP_WAIT1()  asm volatile("cp.async.wait_group 1;"  ::: "memory")

static __device__ __forceinline__ void mma_f16(float c[4],
                                               unsigned a0, unsigned a1,
                                               unsigned a2, unsigned a3,
                                               unsigned b0, unsigned b1) {
    asm volatile(
        "mma.sync.aligned.m16n8k16.row.col.f32.f16.f16.f32 "
        "{%0,%1,%2,%3}, {%4,%5,%6,%7}, {%8,%9}, {%0,%1,%2,%3};"
        : "+f"(c[0]), "+f"(c[1]), "+f"(c[2]), "+f"(c[3])
        : "r"(a0), "r"(a1), "r"(a2), "r"(a3), "r"(b0), "r"(b1));
}

// ---------------------------------------------------------------------------
// fp16 GEMM: C[m,n] = alpha * sum_k A[m,k]*B[n,k] (+bias[n]).
// A,B fp16 K-major. Grid (N/128, M/128, Z). Kd % 64 == 0.
// ---------------------------------------------------------------------------
template<bool OUT_HALF>
__global__ __launch_bounds__(128, 2)
void gemm_f16(const __half* __restrict__ Ap, const __half* __restrict__ Bp,
              const float* __restrict__ bias, void* __restrict__ Cp,
              int ldC, int Kd, size_t sA, size_t sB, size_t sC, float alpha)
{
    extern __shared__ __align__(16) char shp[];

    const int tid  = threadIdx.x;
    const int warp = tid >> 5, lane = tid & 31;
    const int bx = blockIdx.x, by = blockIdx.y, bz = blockIdx.z;
    const int wm = warp >> 1, wn = warp & 1;     // 2x2 warp grid, 64x64 tiles
    const int lq = lane >> 2, lr = lane & 3;

    const __half* Ab = Ap + bz * sA + (size_t)(by * 128) * Kd;
    const __half* Bb = Bp + bz * sB + (size_t)(bx * 128) * Kd;

    const int r0 = tid >> 3, kc = tid & 7;
    const uint32_t swoff = (uint32_t)((kc ^ (r0 & 7)) << 4);
    const uint32_t sb = smem_u32(shp);

    auto issue = [&](int slot, int k0) {
        const uint32_t ab = sb + slot * STAGE_BYTES;
        const uint32_t bb = ab + STAGE_BYTES / 2;
        #pragma unroll
        for (int i = 0; i < 8; i++) {
            const int row = r0 + 16 * i;
            cpasync16(ab + row * 128 + swoff, Ab + (size_t)row * Kd + k0 + kc * 8);
        }
        #pragma unroll
        for (int i = 0; i < 8; i++) {
            const int row = r0 + 16 * i;
            cpasync16(bb + row * 128 + swoff, Bb + (size_t)row * Kd + k0 + kc * 8);
        }
        CP_COMMIT();
    };

    float acc[4][8][4];
    #pragma unroll
    for (int mt = 0; mt < 4; mt++)
        #pragma unroll
        for (int nt = 0; nt < 8; nt++)
            #pragma unroll
            for (int i = 0; i < 4; i++)
                acc[mt][nt][i] = 0.0f;

    issue(0, 0);
    issue(1, 64);

    const int NT = Kd >> 6;
    for (int t = 0; t < NT; t++) {
        CP_WAIT1();
        __syncthreads();
        if (t + 2 < NT) issue((t + 2) % NSTAGE, (t + 2) * 64);
        else            CP_COMMIT();

        const char* As = shp + (t % NSTAGE) * STAGE_BYTES;
        const char* Bs = As + STAGE_BYTES / 2;

        #pragma unroll
        for (int ks = 0; ks < 4; ks++) {
            const int c0 = 2 * ks;
            const uint32_t x0 = (uint32_t)(((c0    ) ^ lq) << 4) + 4 * lr;
            const uint32_t x1 = (uint32_t)(((c0 + 1) ^ lq) << 4) + 4 * lr;
            unsigned af[4][4], bf[8][2];
            #pragma unroll
            for (int mt = 0; mt < 4; mt++) {
                const int mb = (wm * 64 + mt * 16 + lq) * 128;
                af[mt][0] = *(const unsigned*)(As + mb + x0);
                af[mt][1] = *(const unsigned*)(As + mb + 1024 + x0);
                af[mt][2] = *(const unsigned*)(As + mb + x1);
                af[mt][3] = *(const unsigned*)(As + mb + 1024 + x1);
            }
            #pragma unroll
            for (int nt = 0; nt < 8; nt++) {
                const int nb = (wn * 64 + nt * 8 + lq) * 128;
                bf[nt][0] = *(const unsigned*)(Bs + nb + x0);
                bf[nt][1] = *(const unsigned*)(Bs + nb + x1);
            }
            #pragma unroll
            for (int mt = 0; mt < 4; mt++)
                #pragma unroll
                for (int nt = 0; nt < 8; nt++)
                    mma_f16(acc[mt][nt],
                            af[mt][0], af[mt][1], af[mt][2], af[mt][3],
                            bf[nt][0], bf[nt][1]);
        }
    }

    #pragma unroll
    for (int mt = 0; mt < 4; mt++) {
        const int row = by * 128 + wm * 64 + mt * 16 + lq;
        #pragma unroll
        for (int nt = 0; nt < 8; nt++) {
            const int col = bx * 128 + wn * 64 + nt * 8 + 2 * lr;
            const float b0 = bias ? __ldg(&bias[col])     : 0.0f;
            const float b1 = bias ? __ldg(&bias[col + 1]) : 0.0f;
            const float v0 = fmaf(acc[mt][nt][0], alpha, b0);
            const float v1 = fmaf(acc[mt][nt][1], alpha, b1);
            const float v2 = fmaf(acc[mt][nt][2], alpha, b0);
            const float v3 = fmaf(acc[mt][nt][3], alpha, b1);
            const size_t o0 = (size_t)bz * sC + (size_t)row * ldC + col;
            const size_t o1 = (size_t)bz * sC + (size_t)(row + 8) * ldC + col;
            if (OUT_HALF) {
                *(__half2*)((__half*)Cp + o0) = __floats2half2_rn(v0, v1);
                *(__half2*)((__half*)Cp + o1) = __floats2half2_rn(v2, v3);
            } else {
                *(float2*)((float*)Cp + o0) = make_float2(v0, v1);
                *(float2*)((float*)Cp + o1) = make_float2(v2, v3);
            }
        }
    }
}

// ---------------------------------------------------------------------------
// fp32 -> fp16 bulk convert (n % 2048 == 0)
// ---------------------------------------------------------------------------
__global__ __launch_bounds__(256)
void cvt_f2h(const float* __restrict__ s, __half* __restrict__ d, int n)
{
    const int i = (blockIdx.x * 256 + threadIdx.x) * 8;
    if (i >= n) return;
    float4 a = *reinterpret_cast<const float4*>(s + i);
    float4 b = *reinterpret_cast<const float4*>(s + i + 4);
    __half2 h0 = __floats2half2_rn(a.x, a.y);
    __half2 h1 = __floats2half2_rn(a.z, a.w);
    __half2 h2 = __floats2half2_rn(b.x, b.y);
    __half2 h3 = __floats2half2_rn(b.z, b.w);
    uint4 u;
    u.x = *(uint32_t*)&h0; u.y = *(uint32_t*)&h1;
    u.z = *(uint32_t*)&h2; u.w = *(uint32_t*)&h3;
    *reinterpret_cast<uint4*>(d + i) = u;
}

// ---------------------------------------------------------------------------
// fp32 -> fp16 transpose-convert. src [R, C] -> dst [C, R], per batch z.
// 32x32 tiles, block (32, 8). Requires R%32==0, C%32==0.
// ---------------------------------------------------------------------------
__global__ __launch_bounds__(256)
void cvt_f2h_T(const float* __restrict__ src, __half* __restrict__ dst,
               int R, int C)
{
    __shared__ float t[32][33];
    const int c0 = blockIdx.x * 32, r0 = blockIdx.y * 32;
    const size_t sb = (size_t)blockIdx.z * R * C;
    const int tx = threadIdx.x, ty = threadIdx.y;

    #pragma unroll
    for (int i = 0; i < 4; i++)
        t[ty + 8 * i][tx] = src[sb + (size_t)(r0 + ty + 8 * i) * C + c0 + tx];
    __syncthreads();
    #pragma unroll
    for (int i = 0; i < 4; i++)
        dst[sb + (size_t)(c0 + ty + 8 * i) * R + r0 + tx] =
            __float2half_rn(t[tx][ty + 8 * i]);
}

// ---------------------------------------------------------------------------
// bo2[e] = bo[e] + sum_d Wo[e,d] * bv[d]   (fp32, one warp per output)
// Grid 128 x block 256 (8 warps) -> 1024 outputs.
// ---------------------------------------------------------------------------
__global__ __launch_bounds__(256)
void fold_bias(const float* __restrict__ Wo, const float* __restrict__ bv,
               const float* __restrict__ bo, float* __restrict__ bo2)
{
    const int e = blockIdx.x * 8 + (threadIdx.x >> 5);
    const int lane = threadIdx.x & 31;
    float s = 0.0f;
    for (int d = lane; d < D1; d += 32)
        s = fmaf(Wo[(size_t)e * D1 + d], bv[d], s);
    #pragma unroll
    for (int o = 16; o > 0; o >>= 1)
        s += __shfl_xor_sync(0xffffffffu, s, o);
    if (lane == 0) bo2[e] = s + bo[e];
}

// ---------------------------------------------------------------------------
// Row softmax: fp32 in, fp16 out. One 256-thread block per row of LK=2048.
// Vectorized float4 loads / uint4 stores.
// ---------------------------------------------------------------------------
__global__ __launch_bounds__(256)
void softmax_rows_kernel(const float* __restrict__ S, __half* __restrict__ P)
{
    const float* p = S + (size_t)blockIdx.x * LK;
    __half* q = P + (size_t)blockIdx.x * LK;
    const int tid = threadIdx.x;

    float4 a = *reinterpret_cast<const float4*>(p + tid * 8);
    float4 b = *reinterpret_cast<const float4*>(p + tid * 8 + 4);

    float m = fmaxf(fmaxf(fmaxf(a.x, a.y), fmaxf(a.z, a.w)),
                    fmaxf(fmaxf(b.x, b.y), fmaxf(b.z, b.w)));
    #pragma unroll
    for (int o = 16; o > 0; o >>= 1)
        m = fmaxf(m, __shfl_xor_sync(0xffffffffu, m, o));
    __shared__ float sm[8];
    if ((tid & 31) == 0) sm[tid >> 5] = m;
    __syncthreads();
    #pragma unroll
    for (int i = 0; i < 8; i++) m = fmaxf(m, sm[i]);

    a.x = __expf(a.x - m); a.y = __expf(a.y - m);
    a.z = __expf(a.z - m); a.w = __expf(a.w - m);
    b.x = __expf(b.x - m); b.y = __expf(b.y - m);
    b.z = __expf(b.z - m); b.w = __expf(b.w - m);
    float s = a.x + a.y + a.z + a.w + b.x + b.y + b.z + b.w;
    #pragma unroll
    for (int o = 16; o > 0; o >>= 1)
        s += __shfl_xor_sync(0xffffffffu, s, o);
    __shared__ float ss[8];
    if ((tid & 31) == 0) ss[tid >> 5] = s;
    __syncthreads();
    s = 0.0f;
    #pragma unroll
    for (int i = 0; i < 8; i++) s += ss[i];

    const float inv = 1.0f / s;
    __half2 h0 = __floats2half2_rn(a.x * inv, a.y * inv);
    __half2 h1 = __floats2half2_rn(a.z * inv, a.w * inv);
    __half2 h2 = __floats2half2_rn(b.x * inv, b.y * inv);
    __half2 h3 = __floats2half2_rn(b.z * inv, b.w * inv);
    uint4 u;
    u.x = *(uint32_t*)&h0; u.y = *(uint32_t*)&h1;
    u.z = *(uint32_t*)&h2; u.w = *(uint32_t*)&h3;
    *reinterpret_cast<uint4*>(q + tid * 8) = u;
}

// ---------------------------------------------------------------------------
// Host launch
// ---------------------------------------------------------------------------
extern "C" void kernel_launch(void* const* d_in, const int* in_sizes, int n_in,
                              void* d_out, int out_size)
{
    const float* Q  = (const float*)d_in[0];
    const float* K  = (const float*)d_in[1];
    const float* V  = (const float*)d_in[2];
    const float* Wk = (const float*)d_in[3];
    const float* Wv = (const float*)d_in[5];
    const float* bv = (const float*)d_in[6];
    const float* Wo = (const float*)d_in[7];
    const float* bo = (const float*)d_in[8];
    float* out = (float*)d_out;

    void *Qh, *Kh, *WkT, *VhT, *WvT, *Woh, *Wov, *bo2, *Qk, *S, *P, *T;
    cudaGetSymbolAddress(&Qh,  g_Qh);  cudaGetSymbolAddress(&Kh,  g_Kh);
    cudaGetSymbolAddress(&WkT, g_WkT); cudaGetSymbolAddress(&VhT, g_VhT);
    cudaGetSymbolAddress(&WvT, g_WvT); cudaGetSymbolAddress(&Woh, g_Woh);
    cudaGetSymbolAddress(&Wov, g_Wov); cudaGetSymbolAddress(&bo2, g_bo2);
    cudaGetSymbolAddress(&Qk,  g_Qk);  cudaGetSymbolAddress(&S,   g_S);
    cudaGetSymbolAddress(&P,   g_P);   cudaGetSymbolAddress(&T,   g_T);

    cudaFuncSetAttribute(gemm_f16<true>,
        cudaFuncAttributeMaxDynamicSharedMemorySize, SMEM_BYTES);
    cudaFuncSetAttribute(gemm_f16<false>,
        cudaFuncAttributeMaxDynamicSharedMemorySize, SMEM_BYTES);

    // ---- fp32 -> fp16 pre-pass ----
    auto cvt = [&](const float* src, void* dst, size_t n) {
        cvt_f2h<<<(unsigned)(n / 8 / 256), 256>>>(src, (__half*)dst, (int)n);
    };
    cvt(Q,  Qh,  (size_t)BATCH * LQ * D1);
    cvt(K,  Kh,  (size_t)BATCH * LK * D2);
    cvt(Wo, Woh, (size_t)D1 * D1);
    // Wk [D1,D2] -> WkT [D2,D1]; V [B][LK,D2] -> VhT [B][D2,LK]; Wv -> WvT
    cvt_f2h_T<<<dim3(D2/32, D1/32, 1),     dim3(32,8)>>>(Wk, (__half*)WkT, D1, D2);
    cvt_f2h_T<<<dim3(D2/32, LK/32, BATCH), dim3(32,8)>>>(V,  (__half*)VhT, LK, D2);
    cvt_f2h_T<<<dim3(D2/32, D1/32, 1),     dim3(32,8)>>>(Wv, (__half*)WvT, D1, D2);

    // ---- weight/bias folds ----
    fold_bias<<<D1/8, 256>>>(Wo, bv, bo, (float*)bo2);

    const dim3 blk(128);

    // Wov = Woh @ WvT^T  (= Wo @ Wv) -> fp16 [D1,D2]
    gemm_f16<true><<<dim3(D2/128, D1/128, 1), blk, SMEM_BYTES>>>(
        (const __half*)Woh, (const __half*)WvT, nullptr, Wov, D2, D1, 0, 0, 0, 1.0f);

    // 1) Qk = Qh @ WkT^T  (= Q @ Wk; bk dropped, softmax-invariant)
    gemm_f16<true><<<dim3(D2/128, (BATCH*LQ)/128, 1), blk, SMEM_BYTES>>>(
        (const __half*)Qh, (const __half*)WkT, nullptr, Qk, D2, D1, 0, 0, 0, 1.0f);

    // 2) S = (Qk @ Kh^T)/32 -> fp32, per batch
    gemm_f16<false><<<dim3(LK/128, LQ/128, BATCH), blk, SMEM_BYTES>>>(
        (const __half*)Qk, (const __half*)Kh, nullptr, S, LK, D2,
        (size_t)LQ*D2, (size_t)LK*D2, (size_t)LQ*LK, 0.03125f);

    // 3) P = softmax(S) -> fp16
    softmax_rows_kernel<<<BATCH*LQ, 256>>>((const float*)S, (__half*)P);

    // 4) T = P @ VhT^T (= P @ V) -> fp16, per batch
    gemm_f16<true><<<dim3(D2/128, LQ/128, BATCH), blk, SMEM_BYTES>>>(
        (const __half*)P, (const __half*)VhT, nullptr, T, D2, LK,
        (size_t)LQ*LK, (size_t)D2*LK, (size_t)LQ*D2, 1.0f);

    // 5) O = T @ Wov^T + bo2 -> fp32 out  (exact fold of Ctx and O)
    gemm_f16<false><<<dim3(D1/128, (BATCH*LQ)/128, 1), blk, SMEM_BYTES>>>(
        (const __half*)T, (const __half*)Wov, (const float*)bo2, out,
        D1, D2, 0, 0, 0, 1.0f);
}